// round 1
// baseline (speedup 1.0000x reference)
#include <cuda_runtime.h>
#include <math.h>

#define B_   2
#define S_   2048
#define D_   2048
#define H_   16
#define DH_  128
#define P_   16
#define SP_  2064          // S + P
#define BS_  4096          // B * S
#define EPS_ 1e-5f

// ---------------- scratch (static device allocations; allowed) ----------------
__device__ float g_xn [BS_ * D_];           // 32 MB  normalized input
__device__ float g_mix[BS_ * H_];           // gate per (row, head)
__device__ float g_q  [B_ * H_ * S_  * DH_];  // 32 MB
__device__ float g_k  [B_ * H_ * SP_ * DH_];  // 33.8 MB (pmem-prepended)
__device__ float g_v  [B_ * H_ * SP_ * DH_];  // 33.8 MB (mixed + pmem)
__device__ float g_ao [BS_ * D_];           // 32 MB  attention out [B,S,H*DH]

// ---------------- kernel 1: LayerNorm + mix gate ----------------
__global__ __launch_bounds__(256) void ln_mix_kernel(
    const float* __restrict__ x, const float* __restrict__ lng,
    const float* __restrict__ lnb, const float* __restrict__ wmix,
    const float* __restrict__ bmix)
{
    int row = blockIdx.x;
    int tid = threadIdx.x;
    const float4* x4 = (const float4*)(x + (size_t)row * D_);
    float4 v0 = x4[tid];
    float4 v1 = x4[tid + 256];

    float s  = v0.x + v0.y + v0.z + v0.w + v1.x + v1.y + v1.z + v1.w;
    float s2 = v0.x*v0.x + v0.y*v0.y + v0.z*v0.z + v0.w*v0.w
             + v1.x*v1.x + v1.y*v1.y + v1.z*v1.z + v1.w*v1.w;

    #pragma unroll
    for (int o = 16; o; o >>= 1) {
        s  += __shfl_xor_sync(0xffffffffu, s,  o);
        s2 += __shfl_xor_sync(0xffffffffu, s2, o);
    }
    __shared__ float rs[8], rs2[8];
    int warp = tid >> 5, lane = tid & 31;
    if (lane == 0) { rs[warp] = s; rs2[warp] = s2; }
    __syncthreads();
    if (tid == 0) {
        float a = 0.f, b2 = 0.f;
        for (int w = 0; w < 8; w++) { a += rs[w]; b2 += rs2[w]; }
        rs[0] = a; rs2[0] = b2;
    }
    __syncthreads();
    float mu   = rs[0]  * (1.0f / D_);
    float var  = rs2[0] * (1.0f / D_) - mu * mu;
    float rstd = rsqrtf(var + EPS_);

    float xn[8];
    float xv[8] = {v0.x, v0.y, v0.z, v0.w, v1.x, v1.y, v1.z, v1.w};
    int   jidx[8];
    #pragma unroll
    for (int e = 0; e < 8; e++) {
        int j = (e < 4) ? (4 * tid + e) : (1024 + 4 * tid + (e - 4));
        jidx[e] = j;
        xn[e] = (xv[e] - mu) * rstd * lng[j] + lnb[j];
    }
    float4* xo = (float4*)(g_xn + (size_t)row * D_);
    float4 w0 = {xn[0], xn[1], xn[2], xn[3]};
    float4 w1 = {xn[4], xn[5], xn[6], xn[7]};
    xo[tid]       = w0;
    xo[tid + 256] = w1;

    // mix gate: xn @ w_mix  (D x 16)
    float acc[16];
    #pragma unroll
    for (int h = 0; h < 16; h++) acc[h] = 0.f;
    #pragma unroll
    for (int e = 0; e < 8; e++) {
        const float4* wm = (const float4*)(wmix + (size_t)jidx[e] * H_);
        float4 a0 = wm[0], a1 = wm[1], a2 = wm[2], a3 = wm[3];
        float xe = xn[e];
        acc[0]  += xe * a0.x; acc[1]  += xe * a0.y; acc[2]  += xe * a0.z; acc[3]  += xe * a0.w;
        acc[4]  += xe * a1.x; acc[5]  += xe * a1.y; acc[6]  += xe * a1.z; acc[7]  += xe * a1.w;
        acc[8]  += xe * a2.x; acc[9]  += xe * a2.y; acc[10] += xe * a2.z; acc[11] += xe * a2.w;
        acc[12] += xe * a3.x; acc[13] += xe * a3.y; acc[14] += xe * a3.z; acc[15] += xe * a3.w;
    }
    #pragma unroll
    for (int h = 0; h < 16; h++) {
        #pragma unroll
        for (int o = 16; o; o >>= 1) acc[h] += __shfl_xor_sync(0xffffffffu, acc[h], o);
    }
    __shared__ float wsum[8][16];
    if (lane == 0) {
        #pragma unroll
        for (int h = 0; h < 16; h++) wsum[warp][h] = acc[h];
    }
    __syncthreads();
    if (tid < 16) {
        float t = 0.f;
        #pragma unroll
        for (int w = 0; w < 8; w++) t += wsum[w][tid];
        t += bmix[tid];
        g_mix[(size_t)row * H_ + tid] = 1.0f / (1.0f + expf(-t));
    }
}

// ---------------- kernel 2/5: SGEMM 128x128x8, 256 threads, 8x8 micro-tile ----
// MODE 0: A=g_xn, B=w_qkv (N=6144), epilogue scatters into g_q / g_k / g_v (+mix)
// MODE 1: A=g_ao, B=w_out (N=2048), epilogue adds bias, writes d_out
template <int MODE>
__global__ __launch_bounds__(256) void sgemm_kernel(
    const float* __restrict__ Bw, int N,
    const float* __restrict__ vres, const float* __restrict__ bout,
    float* __restrict__ Cout)
{
    __shared__ float As[8][128];
    __shared__ float Bs[8][128];

    const float* A = (MODE == 0) ? g_xn : g_ao;
    int tid = threadIdx.x;
    int tx = tid & 15, ty = tid >> 4;
    int m0 = blockIdx.y * 128, n0 = blockIdx.x * 128;

    float acc[8][8];
    #pragma unroll
    for (int i = 0; i < 8; i++)
        #pragma unroll
        for (int j = 0; j < 8; j++) acc[i][j] = 0.f;

    int arow = tid >> 1, apart = tid & 1;
    int brow = tid >> 5, bcol = tid & 31;
    const int K = D_;

    for (int k0 = 0; k0 < K; k0 += 8) {
        float4 av = *(const float4*)(A  + (size_t)(m0 + arow) * K + k0 + apart * 4);
        float4 bv = *(const float4*)(Bw + (size_t)(k0 + brow) * N + n0 + bcol * 4);
        As[apart * 4 + 0][arow] = av.x;
        As[apart * 4 + 1][arow] = av.y;
        As[apart * 4 + 2][arow] = av.z;
        As[apart * 4 + 3][arow] = av.w;
        *(float4*)&Bs[brow][bcol * 4] = bv;
        __syncthreads();
        #pragma unroll
        for (int k = 0; k < 8; k++) {
            float4 a0 = *(float4*)&As[k][4 * ty];
            float4 a1 = *(float4*)&As[k][64 + 4 * ty];
            float4 b0 = *(float4*)&Bs[k][4 * tx];
            float4 b1 = *(float4*)&Bs[k][64 + 4 * tx];
            float ar[8] = {a0.x, a0.y, a0.z, a0.w, a1.x, a1.y, a1.z, a1.w};
            float br[8] = {b0.x, b0.y, b0.z, b0.w, b1.x, b1.y, b1.z, b1.w};
            #pragma unroll
            for (int i = 0; i < 8; i++)
                #pragma unroll
                for (int j = 0; j < 8; j++) acc[i][j] += ar[i] * br[j];
        }
        __syncthreads();
    }

    #pragma unroll
    for (int i = 0; i < 8; i++) {
        int r = (i < 4) ? (4 * ty + i) : (60 + 4 * ty + i);
        int m = m0 + r;
        int b = m >> 11;        // m / S_
        int s = m & 2047;       // m % S_
        #pragma unroll
        for (int j = 0; j < 8; j++) {
            int c = (j < 4) ? (4 * tx + j) : (60 + 4 * tx + j);
            int n = n0 + c;
            float val = acc[i][j];
            if (MODE == 0) {
                if (n < D_) {
                    int h = n >> 7, d = n & 127;
                    g_q[(((size_t)(b * H_ + h)) * S_ + s) * DH_ + d] = val;
                } else if (n < 2 * D_) {
                    int nn = n - D_;
                    int h = nn >> 7, d = nn & 127;
                    g_k[(((size_t)(b * H_ + h)) * SP_ + P_ + s) * DH_ + d] = val;
                } else {
                    int nn = n - 2 * D_;
                    int h = nn >> 7, d = nn & 127;
                    float mx = g_mix[(size_t)m * H_ + h];
                    float vr = vres[(((size_t)(b * H_ + h)) * S_ + s) * DH_ + d];
                    g_v[(((size_t)(b * H_ + h)) * SP_ + P_ + s) * DH_ + d] =
                        val * (1.0f - mx) + vr * mx;
                }
            } else {
                Cout[(size_t)m * N + n] = val + bout[n];
            }
        }
    }
}

// ---------------- kernel 3: prepend persistent-memory tokens ------------------
__global__ __launch_bounds__(256) void pmem_kernel(const float* __restrict__ pmem)
{
    int i = blockIdx.x * 256 + threadIdx.x;   // over B*H*P*DH = 65536
    int b   = i >> 15;                        // / 32768
    int rem = i & 32767;
    int h  = rem >> 11;                       // / (P*DH)
    int jd = rem & 2047;
    int j  = jd >> 7;
    int d  = jd & 127;
    size_t dst = (((size_t)(b * H_ + h)) * SP_ + j) * DH_ + d;
    g_k[dst] = pmem[rem];
    g_v[dst] = pmem[32768 + rem];
}

// ---------------- kernel 4: flash attention (fp32, online softmax) ------------
__global__ __launch_bounds__(256, 1) void attn_kernel()
{
    extern __shared__ float sm[];
    float* Qs  = sm;                 // [64][128]
    float* Ks  = Qs + 64 * 128;      // [64][128] xor-swizzled columns
    float* Vs  = Ks + 64 * 128;      // [64][128]
    float* Ss  = Vs + 64 * 128;      // [64][65]
    float* msm = Ss + 64 * 65;       // [64]
    float* lsm = msm + 64;           // [64]
    float* csm = lsm + 64;           // [64]

    int tid = threadIdx.x;
    int tx = tid & 15, ty = tid >> 4;
    int qt = blockIdx.x, h = blockIdx.y, b = blockIdx.z;
    int bh = b * H_ + h;
    int qbase = qt * 64;

    for (int t = tid; t < 64 * 32; t += 256) {
        int r = t >> 5, c4 = t & 31;
        float4 v = *(const float4*)(g_q + ((size_t)bh * S_ + qbase + r) * DH_ + 4 * c4);
        *(float4*)&Qs[r * 128 + 4 * c4] = v;
    }
    if (tid < 64) { msm[tid] = -INFINITY; lsm[tid] = 0.f; }

    float o[4][8];
    #pragma unroll
    for (int i = 0; i < 4; i++)
        #pragma unroll
        for (int d = 0; d < 8; d++) o[i][d] = 0.f;

    const float scale = 0.08838834764831845f;   // DH^-0.5
    int kv_end = P_ + qbase + 64;
    int ntiles = (kv_end + 63) >> 6;
    int xk = (tx & 7) << 2;

    for (int t = 0; t < ntiles; t++) {
        int j0 = t << 6;
        for (int u = tid; u < 64 * 32; u += 256) {
            int r = u >> 5, c4 = u & 31;
            int jg = j0 + r; if (jg > SP_ - 1) jg = SP_ - 1;   // clamp (masked anyway)
            size_t base = ((size_t)bh * SP_ + jg) * DH_ + 4 * c4;
            float4 kv = *(const float4*)(g_k + base);
            float4 vv = *(const float4*)(g_v + base);
            int sc = (4 * c4) ^ (((r >> 2) & 7) << 2);
            *(float4*)&Ks[r * 128 + sc]     = kv;
            *(float4*)&Vs[r * 128 + 4 * c4] = vv;
        }
        __syncthreads();

        // ---- S = Q K^T ----
        float sacc[4][4];
        #pragma unroll
        for (int i = 0; i < 4; i++)
            #pragma unroll
            for (int j = 0; j < 4; j++) sacc[i][j] = 0.f;
        #pragma unroll 8
        for (int d4 = 0; d4 < 32; d4++) {
            float4 q[4], k[4];
            #pragma unroll
            for (int i = 0; i < 4; i++) q[i] = *(float4*)&Qs[(4 * ty + i) * 128 + 4 * d4];
            #pragma unroll
            for (int j = 0; j < 4; j++) k[j] = *(float4*)&Ks[(4 * tx + j) * 128 + ((4 * d4) ^ xk)];
            #pragma unroll
            for (int i = 0; i < 4; i++)
                #pragma unroll
                for (int j = 0; j < 4; j++)
                    sacc[i][j] += q[i].x * k[j].x + q[i].y * k[j].y
                                + q[i].z * k[j].z + q[i].w * k[j].w;
        }
        #pragma unroll
        for (int i = 0; i < 4; i++) {
            int r = 4 * ty + i;
            int ig = qbase + r;
            #pragma unroll
            for (int j = 0; j < 4; j++) {
                int c = 4 * tx + j;
                int jg = j0 + c;
                float sv = sacc[i][j] * scale;
                if (jg >= P_ && (jg - P_) > ig) sv = -1e30f;
                Ss[r * 65 + c] = sv;
            }
        }
        __syncthreads();

        // ---- online softmax (4 lanes per row) ----
        {
            int row = tid >> 2, sub = tid & 3;
            float mloc = -1e30f;
            #pragma unroll
            for (int e = 0; e < 16; e++) mloc = fmaxf(mloc, Ss[row * 65 + sub * 16 + e]);
            mloc = fmaxf(mloc, __shfl_xor_sync(0xffffffffu, mloc, 1));
            mloc = fmaxf(mloc, __shfl_xor_sync(0xffffffffu, mloc, 2));
            float mold = msm[row];
            float mnew = fmaxf(mold, mloc);
            float corr = __expf(mold - mnew);
            float ps = 0.f;
            #pragma unroll
            for (int e = 0; e < 16; e++) {
                float p = __expf(Ss[row * 65 + sub * 16 + e] - mnew);
                Ss[row * 65 + sub * 16 + e] = p;
                ps += p;
            }
            ps += __shfl_xor_sync(0xffffffffu, ps, 1);
            ps += __shfl_xor_sync(0xffffffffu, ps, 2);
            if (sub == 0) { msm[row] = mnew; lsm[row] = lsm[row] * corr + ps; csm[row] = corr; }
        }
        __syncthreads();

        // ---- O = O*corr + P V ----
        #pragma unroll
        for (int i = 0; i < 4; i++) {
            float cr = csm[4 * ty + i];
            #pragma unroll
            for (int d = 0; d < 8; d++) o[i][d] *= cr;
        }
        #pragma unroll 4
        for (int j = 0; j < 64; j++) {
            float4 va = *(float4*)&Vs[j * 128 + 8 * tx];
            float4 vb = *(float4*)&Vs[j * 128 + 8 * tx + 4];
            #pragma unroll
            for (int i = 0; i < 4; i++) {
                float p = Ss[(4 * ty + i) * 65 + j];
                o[i][0] += p * va.x; o[i][1] += p * va.y;
                o[i][2] += p * va.z; o[i][3] += p * va.w;
                o[i][4] += p * vb.x; o[i][5] += p * vb.y;
                o[i][6] += p * vb.z; o[i][7] += p * vb.w;
            }
        }
        __syncthreads();
    }

    #pragma unroll
    for (int i = 0; i < 4; i++) {
        int r = 4 * ty + i;
        float linv = 1.0f / lsm[r];
        int s = qbase + r;
        float* dst = g_ao + ((size_t)(b * S_ + s)) * D_ + h * DH_ + 8 * tx;
        float4 oa = {o[i][0] * linv, o[i][1] * linv, o[i][2] * linv, o[i][3] * linv};
        float4 ob = {o[i][4] * linv, o[i][5] * linv, o[i][6] * linv, o[i][7] * linv};
        *(float4*)dst       = oa;
        *(float4*)(dst + 4) = ob;
    }
}

// ---------------- launch ------------------------------------------------------
extern "C" void kernel_launch(void* const* d_in, const int* in_sizes, int n_in,
                              void* d_out, int out_size)
{
    const float* x    = (const float*)d_in[0];
    const float* vres = (const float*)d_in[1];
    const float* lng  = (const float*)d_in[2];
    const float* lnb  = (const float*)d_in[3];
    const float* wqkv = (const float*)d_in[4];
    const float* wout = (const float*)d_in[5];
    const float* bout = (const float*)d_in[6];
    const float* wmix = (const float*)d_in[7];
    const float* bmix = (const float*)d_in[8];
    const float* pmem = (const float*)d_in[9];
    float* out = (float*)d_out;

    const int SMEM_ATTN = (3 * 64 * 128 + 64 * 65 + 3 * 64) * (int)sizeof(float);
    cudaFuncSetAttribute(attn_kernel, cudaFuncAttributeMaxDynamicSharedMemorySize, SMEM_ATTN);

    ln_mix_kernel<<<BS_, 256>>>(x, lng, lnb, wmix, bmix);
    pmem_kernel<<<256, 256>>>(pmem);
    {
        dim3 g(3 * D_ / 128, BS_ / 128);   // (48, 32)
        sgemm_kernel<0><<<g, 256>>>(wqkv, 3 * D_, vres, nullptr, nullptr);
    }
    {
        dim3 g(S_ / 64, H_, B_);           // (32, 16, 2)
        attn_kernel<<<g, 256, SMEM_ATTN>>>();
    }
    {
        dim3 g(D_ / 128, BS_ / 128);       // (16, 32)
        sgemm_kernel<1><<<g, 256>>>(wout, D_, nullptr, bout, out);
    }
}

// round 7
// speedup vs baseline: 1.6926x; 1.6926x over previous
// Round 7: resubmission of round-6 source (round 6 hit a broker/container
// infra failure and never ran). Fix under test: transconv destinations are
// template-resolved in device code; no __device__ symbol is passed from host.
#include <cuda_runtime.h>
#include <math.h>

#define B_   2
#define S_   2048
#define D_   2048
#define H_   16
#define DH_  128
#define P_   16
#define SP_  2064
#define BS_  4096
#define EPS_ 1e-5f

// ---------------- static scratch ----------------
__device__ __align__(16) unsigned short g_A1h[BS_ * D_];      // xn hi (bf16 bits)
__device__ __align__(16) unsigned short g_A1l[BS_ * D_];      // xn lo
__device__ __align__(16) unsigned short g_Bqh[3 * D_ * D_];   // w_qkv^T hi [6144][2048]
__device__ __align__(16) unsigned short g_Bql[3 * D_ * D_];
__device__ __align__(16) unsigned short g_Boh[D_ * D_];       // w_out^T hi [2048][2048]
__device__ __align__(16) unsigned short g_Bol[D_ * D_];
__device__ __align__(16) unsigned short g_A2h[BS_ * D_];      // attn out hi
__device__ __align__(16) unsigned short g_A2l[BS_ * D_];
__device__ float g_mix[BS_ * H_];
__device__ float g_q[B_ * H_ * S_  * DH_];
__device__ float g_k[B_ * H_ * SP_ * DH_];
__device__ float g_v[B_ * H_ * SP_ * DH_];

// ---------------- helpers ----------------
__device__ __forceinline__ unsigned smem_u32(const void* p) {
    unsigned a;
    asm("{ .reg .u64 t; cvta.to.shared.u64 t, %1; cvt.u32.u64 %0, t; }" : "=r"(a) : "l"(p));
    return a;
}
__device__ __forceinline__ void cp16(unsigned s, const void* g) {
    asm volatile("cp.async.cg.shared.global [%0], [%1], 16;" :: "r"(s), "l"(g));
}
#define CP_COMMIT() asm volatile("cp.async.commit_group;" ::: "memory")
#define CP_WAIT1()  asm volatile("cp.async.wait_group 1;" ::: "memory")
#define CP_WAIT0()  asm volatile("cp.async.wait_group 0;" ::: "memory")

#define LDM4(d0, d1, d2, d3, addr) \
    asm volatile("ldmatrix.sync.aligned.m8n8.x4.shared.b16 {%0,%1,%2,%3}, [%4];" \
        : "=r"(d0), "=r"(d1), "=r"(d2), "=r"(d3) : "r"(addr))

#define MMA_BF16(c0, c1, c2, c3, a0, a1, a2, a3, b0, b1) \
    asm volatile("mma.sync.aligned.m16n8k16.row.col.f32.bf16.bf16.f32 " \
        "{%0,%1,%2,%3}, {%4,%5,%6,%7}, {%8,%9}, {%0,%1,%2,%3};" \
        : "+f"(c0), "+f"(c1), "+f"(c2), "+f"(c3) \
        : "r"(a0), "r"(a1), "r"(a2), "r"(a3), "r"(b0), "r"(b1))

__device__ __forceinline__ unsigned swz(unsigned off) {   // 64B rows
    return off ^ (((off >> 7) & 3u) << 4);
}

// bf16 split, RNE, pure bit ops. hb/lb are unsigned lvalues (16-bit payload).
#define SPLIT2(v, hb, lb) do { \
    float _v = (v); \
    unsigned _u = __float_as_uint(_v); \
    hb = (_u + 0x7FFFu + ((_u >> 16) & 1u)) >> 16; \
    float _r = _v - __uint_as_float(hb << 16); \
    unsigned _w = __float_as_uint(_r); \
    lb = (_w + 0x7FFFu + ((_w >> 16) & 1u)) >> 16; \
} while (0)

// ---------------- kernel 1: LayerNorm + mix gate + bf16 split ----------------
__global__ __launch_bounds__(256) void ln_mix_kernel(
    const float* __restrict__ x, const float* __restrict__ lng,
    const float* __restrict__ lnb, const float* __restrict__ wmix,
    const float* __restrict__ bmix)
{
    int row = blockIdx.x;
    int tid = threadIdx.x;
    const float4* x4 = (const float4*)(x + (size_t)row * D_);
    float4 v0 = x4[tid];
    float4 v1 = x4[tid + 256];

    float s  = v0.x + v0.y + v0.z + v0.w + v1.x + v1.y + v1.z + v1.w;
    float s2 = v0.x*v0.x + v0.y*v0.y + v0.z*v0.z + v0.w*v0.w
             + v1.x*v1.x + v1.y*v1.y + v1.z*v1.z + v1.w*v1.w;
    #pragma unroll
    for (int o = 16; o; o >>= 1) {
        s  += __shfl_xor_sync(0xffffffffu, s,  o);
        s2 += __shfl_xor_sync(0xffffffffu, s2, o);
    }
    __shared__ float rs[8], rs2[8];
    int warp = tid >> 5, lane = tid & 31;
    if (lane == 0) { rs[warp] = s; rs2[warp] = s2; }
    __syncthreads();
    if (tid == 0) {
        float a = 0.f, b2 = 0.f;
        for (int w = 0; w < 8; w++) { a += rs[w]; b2 += rs2[w]; }
        rs[0] = a; rs2[0] = b2;
    }
    __syncthreads();
    float mu   = rs[0]  * (1.0f / D_);
    float var  = rs2[0] * (1.0f / D_) - mu * mu;
    float rstd = rsqrtf(var + EPS_);

    float xn[8];
    float xv[8] = {v0.x, v0.y, v0.z, v0.w, v1.x, v1.y, v1.z, v1.w};
    int jidx[8];
    #pragma unroll
    for (int e = 0; e < 8; e++) {
        int j = (e < 4) ? (4 * tid + e) : (1024 + 4 * tid + (e - 4));
        jidx[e] = j;
        xn[e] = (xv[e] - mu) * rstd * lng[j] + lnb[j];
    }
    unsigned hb[8], lb[8];
    #pragma unroll
    for (int e = 0; e < 8; e++) SPLIT2(xn[e], hb[e], lb[e]);
    size_t base = (size_t)row * D_;
    *(uint2*)(g_A1h + base + 4 * tid) =
        make_uint2(hb[0] | (hb[1] << 16), hb[2] | (hb[3] << 16));
    *(uint2*)(g_A1l + base + 4 * tid) =
        make_uint2(lb[0] | (lb[1] << 16), lb[2] | (lb[3] << 16));
    *(uint2*)(g_A1h + base + 1024 + 4 * tid) =
        make_uint2(hb[4] | (hb[5] << 16), hb[6] | (hb[7] << 16));
    *(uint2*)(g_A1l + base + 1024 + 4 * tid) =
        make_uint2(lb[4] | (lb[5] << 16), lb[6] | (lb[7] << 16));

    float acc[16];
    #pragma unroll
    for (int h = 0; h < 16; h++) acc[h] = 0.f;
    #pragma unroll
    for (int e = 0; e < 8; e++) {
        const float4* wm = (const float4*)(wmix + (size_t)jidx[e] * H_);
        float4 a0 = wm[0], a1 = wm[1], a2 = wm[2], a3 = wm[3];
        float xe = xn[e];
        acc[0]  += xe * a0.x; acc[1]  += xe * a0.y; acc[2]  += xe * a0.z; acc[3]  += xe * a0.w;
        acc[4]  += xe * a1.x; acc[5]  += xe * a1.y; acc[6]  += xe * a1.z; acc[7]  += xe * a1.w;
        acc[8]  += xe * a2.x; acc[9]  += xe * a2.y; acc[10] += xe * a2.z; acc[11] += xe * a2.w;
        acc[12] += xe * a3.x; acc[13] += xe * a3.y; acc[14] += xe * a3.z; acc[15] += xe * a3.w;
    }
    #pragma unroll
    for (int h = 0; h < 16; h++) {
        #pragma unroll
        for (int o = 16; o; o >>= 1) acc[h] += __shfl_xor_sync(0xffffffffu, acc[h], o);
    }
    __shared__ float wsum[8][16];
    if (lane == 0) {
        #pragma unroll
        for (int h = 0; h < 16; h++) wsum[warp][h] = acc[h];
    }
    __syncthreads();
    if (tid < 16) {
        float t = 0.f;
        #pragma unroll
        for (int w = 0; w < 8; w++) t += wsum[w][tid];
        t += bmix[tid];
        g_mix[(size_t)row * H_ + tid] = 1.0f / (1.0f + expf(-t));
    }
}

// ---------------- transpose + split weights (templated: NO device symbols
// passed from host — destinations resolved in device code) -------------------
template <int WHICH>   // 0: w_qkv -> g_Bq{h,l} (Cols=6144), 1: w_out -> g_Bo{h,l} (Cols=2048)
__global__ __launch_bounds__(256) void transconv_kernel(const float* __restrict__ src)
{
    const int Rows = D_;
    const int Cols = (WHICH == 0) ? 3 * D_ : D_;
    unsigned short* __restrict__ dhi = (WHICH == 0) ? g_Bqh : g_Boh;
    unsigned short* __restrict__ dlo = (WHICH == 0) ? g_Bql : g_Bol;

    __shared__ float tile[32][33];
    int bx = blockIdx.x * 32;
    int by = blockIdx.y * 32;
    int tx = threadIdx.x & 31, ty = threadIdx.x >> 5;
    #pragma unroll
    for (int i = 0; i < 32; i += 8)
        tile[ty + i][tx] = src[(size_t)(by + ty + i) * Cols + bx + tx];
    __syncthreads();
    #pragma unroll
    for (int i = 0; i < 32; i += 8) {
        unsigned h, l;
        SPLIT2(tile[tx][ty + i], h, l);
        size_t o = (size_t)(bx + ty + i) * Rows + by + tx;
        dhi[o] = (unsigned short)h;
        dlo[o] = (unsigned short)l;
    }
}

// ---------------- pmem prepend ----------------
__global__ __launch_bounds__(256) void pmem_kernel(const float* __restrict__ pmem)
{
    int i = blockIdx.x * 256 + threadIdx.x;
    int b = i >> 15;
    int rem = i & 32767;
    int h = rem >> 11;
    int jd = rem & 2047;
    int j = jd >> 7, d = jd & 127;
    size_t dst = (((size_t)(b * H_ + h)) * SP_ + j) * DH_ + d;
    g_k[dst] = pmem[rem];
    g_v[dst] = pmem[32768 + rem];
}

// ---------------- HMMA bf16x3 GEMM: 128x128x32 tile, cp.async 3-stage --------
#define BK_ 32
#define NCH (D_ / BK_)          // 64 chunks
#define STG 32768               // Ah 8K | Al 8K | Bh 8K | Bl 8K
#define GEMM_SMEM (3 * STG + 1024)

#define LOAD_STAGE(st, k0) do { \
    unsigned _sp = sbase + (st) * STG; \
    size_t _ga0 = (size_t)(m0 + r0c) * D_ + (k0) + k0c * 8; \
    size_t _ga1 = (size_t)(m0 + r1c) * D_ + (k0) + k0c * 8; \
    size_t _gb0 = (size_t)(n0 + r0c) * D_ + (k0) + k0c * 8; \
    size_t _gb1 = (size_t)(n0 + r1c) * D_ + (k0) + k0c * 8; \
    cp16(_sp + so0,         Ah + _ga0);  cp16(_sp + so1,         Ah + _ga1); \
    cp16(_sp + 8192 + so0,  Al + _ga0);  cp16(_sp + 8192 + so1,  Al + _ga1); \
    cp16(_sp + 16384 + so0, Bh + _gb0);  cp16(_sp + 16384 + so1, Bh + _gb1); \
    cp16(_sp + 24576 + so0, Bl + _gb0);  cp16(_sp + 24576 + so1, Bl + _gb1); \
} while (0)

template <int MODE>
__global__ __launch_bounds__(256, 1) void gemm_kernel(
    const float* __restrict__ vres, const float* __restrict__ bout,
    float* __restrict__ Cout)
{
    extern __shared__ char dynsm[];
    unsigned braw = smem_u32(dynsm);
    unsigned sbase = (braw + 1023) & ~1023u;

    int tid = threadIdx.x;
    int lane = tid & 31, wid = tid >> 5;
    int warp_m = wid & 3, warp_n = wid >> 2;
    int m0 = blockIdx.y * 128, n0 = blockIdx.x * 128;
    int wm = warp_m * 32, wn = warp_n * 64;

    const unsigned short* Ah = (MODE == 0) ? g_A1h : g_A2h;
    const unsigned short* Al = (MODE == 0) ? g_A1l : g_A2l;
    const unsigned short* Bh = (MODE == 0) ? g_Bqh : g_Boh;
    const unsigned short* Bl = (MODE == 0) ? g_Bql : g_Bol;

    int r0c = tid >> 2, k0c = tid & 3;
    int r1c = (tid + 256) >> 2;
    unsigned so0 = swz((unsigned)(r0c * 64 + k0c * 16));
    unsigned so1 = swz((unsigned)(r1c * 64 + k0c * 16));

    int t4 = lane >> 3, lr = lane & 7;
    int a_row = ((t4 & 1) << 3) + lr;
    int a_cb  = (t4 >> 1) << 4;
    int b_row = ((t4 >> 1) << 3) + lr;
    int b_cb  = (t4 & 1) << 4;

    float acc[2][8][4];
    #pragma unroll
    for (int i = 0; i < 2; i++)
        #pragma unroll
        for (int j = 0; j < 8; j++)
            #pragma unroll
            for (int q = 0; q < 4; q++) acc[i][j][q] = 0.f;

    LOAD_STAGE(0, 0); CP_COMMIT();
    LOAD_STAGE(1, BK_); CP_COMMIT();

    #pragma unroll 1
    for (int c = 0; c < NCH; c++) {
        if (c + 2 < NCH) CP_WAIT1(); else CP_WAIT0();
        __syncthreads();
        if (c + 2 < NCH) { LOAD_STAGE((c + 2) % 3, (c + 2) * BK_); CP_COMMIT(); }

        unsigned sp = sbase + (c % 3) * STG;
        unsigned sAh = sp, sAl = sp + 8192, sBh = sp + 16384, sBl = sp + 24576;

        #pragma unroll
        for (int ks = 0; ks < 2; ks++) {
            unsigned bh[8][2], bl[8][2];
            #pragma unroll
            for (int np = 0; np < 4; np++) {
                unsigned off = swz((unsigned)((wn + np * 16 + b_row) * 64 + ks * 32 + b_cb));
                LDM4(bh[2*np][0], bh[2*np][1], bh[2*np+1][0], bh[2*np+1][1], sBh + off);
                LDM4(bl[2*np][0], bl[2*np][1], bl[2*np+1][0], bl[2*np+1][1], sBl + off);
            }
            #pragma unroll
            for (int mt = 0; mt < 2; mt++) {
                unsigned ah0, ah1, ah2, ah3, al0, al1, al2, al3;
                unsigned off = swz((unsigned)((wm + mt * 16 + a_row) * 64 + ks * 32 + a_cb));
                LDM4(ah0, ah1, ah2, ah3, sAh + off);
                LDM4(al0, al1, al2, al3, sAl + off);
                #pragma unroll
                for (int nt = 0; nt < 8; nt++) {
                    MMA_BF16(acc[mt][nt][0], acc[mt][nt][1], acc[mt][nt][2], acc[mt][nt][3],
                             ah0, ah1, ah2, ah3, bh[nt][0], bh[nt][1]);
                    MMA_BF16(acc[mt][nt][0], acc[mt][nt][1], acc[mt][nt][2], acc[mt][nt][3],
                             ah0, ah1, ah2, ah3, bl[nt][0], bl[nt][1]);
                    MMA_BF16(acc[mt][nt][0], acc[mt][nt][1], acc[mt][nt][2], acc[mt][nt][3],
                             al0, al1, al2, al3, bh[nt][0], bh[nt][1]);
                }
            }
        }
        __syncthreads();
    }

    // ---- epilogue: direct scatter ----
    #pragma unroll
    for (int mt = 0; mt < 2; mt++) {
        #pragma unroll
        for (int nt = 0; nt < 8; nt++) {
            int mrow0 = m0 + wm + mt * 16 + (lane >> 2);
            int n     = n0 + wn + nt * 8 + 2 * (lane & 3);
            #pragma unroll
            for (int half = 0; half < 2; half++) {
                int m = mrow0 + half * 8;
                float va = acc[mt][nt][2 * half];
                float vb = acc[mt][nt][2 * half + 1];
                int b = m >> 11, sg = m & 2047;
                if (MODE == 0) {
                    int seg = n >> 11;
                    int nn = n & 2047;
                    int h = nn >> 7, d = nn & 127;
                    if (seg == 0) {
                        *(float2*)(g_q + (((size_t)(b * H_ + h)) * S_ + sg) * DH_ + d) =
                            make_float2(va, vb);
                    } else if (seg == 1) {
                        *(float2*)(g_k + (((size_t)(b * H_ + h)) * SP_ + P_ + sg) * DH_ + d) =
                            make_float2(va, vb);
                    } else {
                        float mx = g_mix[(size_t)m * H_ + h];
                        float2 vr = *(const float2*)(vres + (((size_t)(b * H_ + h)) * S_ + sg) * DH_ + d);
                        float om = 1.0f - mx;
                        *(float2*)(g_v + (((size_t)(b * H_ + h)) * SP_ + P_ + sg) * DH_ + d) =
                            make_float2(va * om + vr.x * mx, vb * om + vr.y * mx);
                    }
                } else {
                    *(float2*)(Cout + (size_t)m * D_ + n) =
                        make_float2(va + bout[n], vb + bout[n + 1]);
                }
            }
        }
    }
}

// ---------------- flash attention (fp32; bf16-split epilogue) -----------------
__global__ __launch_bounds__(256, 1) void attn_kernel()
{
    extern __shared__ float sm[];
    float* Qs  = sm;
    float* Ks  = Qs + 64 * 128;
    float* Vs  = Ks + 64 * 128;
    float* Ss  = Vs + 64 * 128;
    float* msm = Ss + 64 * 65;
    float* lsm = msm + 64;
    float* csm = lsm + 64;

    int tid = threadIdx.x;
    int tx = tid & 15, ty = tid >> 4;
    int qt = blockIdx.x, h = blockIdx.y, b = blockIdx.z;
    int bh = b * H_ + h;
    int qbase = qt * 64;

    for (int t = tid; t < 64 * 32; t += 256) {
        int r = t >> 5, c4 = t & 31;
        float4 v = *(const float4*)(g_q + ((size_t)bh * S_ + qbase + r) * DH_ + 4 * c4);
        *(float4*)&Qs[r * 128 + 4 * c4] = v;
    }
    if (tid < 64) { msm[tid] = -INFINITY; lsm[tid] = 0.f; }

    float o[4][8];
    #pragma unroll
    for (int i = 0; i < 4; i++)
        #pragma unroll
        for (int d = 0; d < 8; d++) o[i][d] = 0.f;

    const float scale = 0.08838834764831845f;
    int kv_end = P_ + qbase + 64;
    int ntiles = (kv_end + 63) >> 6;
    int xk = (tx & 7) << 2;

    for (int t = 0; t < ntiles; t++) {
        int j0 = t << 6;
        for (int u = tid; u < 64 * 32; u += 256) {
            int r = u >> 5, c4 = u & 31;
            int jg = j0 + r; if (jg > SP_ - 1) jg = SP_ - 1;
            size_t base = ((size_t)bh * SP_ + jg) * DH_ + 4 * c4;
            float4 kv = *(const float4*)(g_k + base);
            float4 vv = *(const float4*)(g_v + base);
            int sc = (4 * c4) ^ (((r >> 2) & 7) << 2);
            *(float4*)&Ks[r * 128 + sc]     = kv;
            *(float4*)&Vs[r * 128 + 4 * c4] = vv;
        }
        __syncthreads();

        float sacc[4][4];
        #pragma unroll
        for (int i = 0; i < 4; i++)
            #pragma unroll
            for (int j = 0; j < 4; j++) sacc[i][j] = 0.f;
        #pragma unroll 8
        for (int d4 = 0; d4 < 32; d4++) {
            float4 q[4], k[4];
            #pragma unroll
            for (int i = 0; i < 4; i++) q[i] = *(float4*)&Qs[(4 * ty + i) * 128 + 4 * d4];
            #pragma unroll
            for (int j = 0; j < 4; j++) k[j] = *(float4*)&Ks[(4 * tx + j) * 128 + ((4 * d4) ^ xk)];
            #pragma unroll
            for (int i = 0; i < 4; i++)
                #pragma unroll
                for (int j = 0; j < 4; j++)
                    sacc[i][j] += q[i].x * k[j].x + q[i].y * k[j].y
                                + q[i].z * k[j].z + q[i].w * k[j].w;
        }
        #pragma unroll
        for (int i = 0; i < 4; i++) {
            int r = 4 * ty + i;
            int ig = qbase + r;
            #pragma unroll
            for (int j = 0; j < 4; j++) {
                int c = 4 * tx + j;
                int jg = j0 + c;
                float sv = sacc[i][j] * scale;
                if (jg >= P_ && (jg - P_) > ig) sv = -1e30f;
                Ss[r * 65 + c] = sv;
            }
        }
        __syncthreads();

        {
            int row = tid >> 2, sub = tid & 3;
            float mloc = -1e30f;
            #pragma unroll
            for (int e = 0; e < 16; e++) mloc = fmaxf(mloc, Ss[row * 65 + sub * 16 + e]);
            mloc = fmaxf(mloc, __shfl_xor_sync(0xffffffffu, mloc, 1));
            mloc = fmaxf(mloc, __shfl_xor_sync(0xffffffffu, mloc, 2));
            float mold = msm[row];
            float mnew = fmaxf(mold, mloc);
            float corr = __expf(mold - mnew);
            float ps = 0.f;
            #pragma unroll
            for (int e = 0; e < 16; e++) {
                float p = __expf(Ss[row * 65 + sub * 16 + e] - mnew);
                Ss[row * 65 + sub * 16 + e] = p;
                ps += p;
            }
            ps += __shfl_xor_sync(0xffffffffu, ps, 1);
            ps += __shfl_xor_sync(0xffffffffu, ps, 2);
            if (sub == 0) { msm[row] = mnew; lsm[row] = lsm[row] * corr + ps; csm[row] = corr; }
        }
        __syncthreads();

        #pragma unroll
        for (int i = 0; i < 4; i++) {
            float cr = csm[4 * ty + i];
            #pragma unroll
            for (int d = 0; d < 8; d++) o[i][d] *= cr;
        }
        #pragma unroll 4
        for (int j = 0; j < 64; j++) {
            float4 va = *(float4*)&Vs[j * 128 + 8 * tx];
            float4 vb = *(float4*)&Vs[j * 128 + 8 * tx + 4];
            #pragma unroll
            for (int i = 0; i < 4; i++) {
                float p = Ss[(4 * ty + i) * 65 + j];
                o[i][0] += p * va.x; o[i][1] += p * va.y;
                o[i][2] += p * va.z; o[i][3] += p * va.w;
                o[i][4] += p * vb.x; o[i][5] += p * vb.y;
                o[i][6] += p * vb.z; o[i][7] += p * vb.w;
            }
        }
        __syncthreads();
    }

    #pragma unroll
    for (int i = 0; i < 4; i++) {
        int r = 4 * ty + i;
        float linv = 1.0f / lsm[r];
        int s = qbase + r;
        size_t rowoff = ((size_t)(b * S_ + s)) * D_ + h * DH_ + 8 * tx;
        unsigned hb[8], lb[8];
        #pragma unroll
        for (int d = 0; d < 8; d++) SPLIT2(o[i][d] * linv, hb[d], lb[d]);
        uint4 uh, ul;
        uh.x = hb[0] | (hb[1] << 16);
        uh.y = hb[2] | (hb[3] << 16);
        uh.z = hb[4] | (hb[5] << 16);
        uh.w = hb[6] | (hb[7] << 16);
        ul.x = lb[0] | (lb[1] << 16);
        ul.y = lb[2] | (lb[3] << 16);
        ul.z = lb[4] | (lb[5] << 16);
        ul.w = lb[6] | (lb[7] << 16);
        *(uint4*)(g_A2h + rowoff) = uh;
        *(uint4*)(g_A2l + rowoff) = ul;
    }
}

// ---------------- launch ------------------------------------------------------
extern "C" void kernel_launch(void* const* d_in, const int* in_sizes, int n_in,
                              void* d_out, int out_size)
{
    const float* x    = (const float*)d_in[0];
    const float* vres = (const float*)d_in[1];
    const float* lng  = (const float*)d_in[2];
    const float* lnb  = (const float*)d_in[3];
    const float* wqkv = (const float*)d_in[4];
    const float* wout = (const float*)d_in[5];
    const float* bout = (const float*)d_in[6];
    const float* wmix = (const float*)d_in[7];
    const float* bmix = (const float*)d_in[8];
    const float* pmem = (const float*)d_in[9];
    float* out = (float*)d_out;

    const int SMEM_ATTN = (3 * 64 * 128 + 64 * 65 + 3 * 64) * (int)sizeof(float);
    cudaFuncSetAttribute(attn_kernel, cudaFuncAttributeMaxDynamicSharedMemorySize, SMEM_ATTN);
    cudaFuncSetAttribute(gemm_kernel<0>, cudaFuncAttributeMaxDynamicSharedMemorySize, GEMM_SMEM);
    cudaFuncSetAttribute(gemm_kernel<1>, cudaFuncAttributeMaxDynamicSharedMemorySize, GEMM_SMEM);

    ln_mix_kernel<<<BS_, 256>>>(x, lng, lnb, wmix, bmix);
    transconv_kernel<0><<<dim3(3 * D_ / 32, D_ / 32), 256>>>(wqkv);
    transconv_kernel<1><<<dim3(D_ / 32, D_ / 32), 256>>>(wout);
    pmem_kernel<<<256, 256>>>(pmem);
    gemm_kernel<0><<<dim3(3 * D_ / 128, BS_ / 128), 256, GEMM_SMEM>>>(vres, nullptr, nullptr);
    attn_kernel<<<dim3(S_ / 64, H_, B_), 256, SMEM_ATTN>>>();
    gemm_kernel<1><<<dim3(D_ / 128, BS_ / 128), 256, GEMM_SMEM>>>(nullptr, bout, out);
}

// round 8
// speedup vs baseline: 2.5040x; 1.4794x over previous
#include <cuda_runtime.h>
#include <math.h>

#define B_   2
#define S_   2048
#define D_   2048
#define H_   16
#define DH_  128
#define P_   16
#define SP_  2064
#define BS_  4096
#define EPS_ 1e-5f

// ---------------- static scratch ----------------
__device__ __align__(16) unsigned short g_A1h[BS_ * D_];      // xn hi
__device__ __align__(16) unsigned short g_A1l[BS_ * D_];      // xn lo
__device__ __align__(16) unsigned short g_Bqh[3 * D_ * D_];   // w_qkv^T hi
__device__ __align__(16) unsigned short g_Bql[3 * D_ * D_];
__device__ __align__(16) unsigned short g_Boh[D_ * D_];       // w_out^T hi
__device__ __align__(16) unsigned short g_Bol[D_ * D_];
__device__ __align__(16) unsigned short g_A2h[BS_ * D_];      // attn out hi
__device__ __align__(16) unsigned short g_A2l[BS_ * D_];
__device__ float g_mix[BS_ * H_];
__device__ __align__(16) unsigned short g_qh[B_ * H_ * S_  * DH_];
__device__ __align__(16) unsigned short g_ql[B_ * H_ * S_  * DH_];
__device__ __align__(16) unsigned short g_kh[B_ * H_ * SP_ * DH_];
__device__ __align__(16) unsigned short g_kl[B_ * H_ * SP_ * DH_];
__device__ __align__(16) unsigned short g_vh[B_ * H_ * SP_ * DH_];
__device__ __align__(16) unsigned short g_vl[B_ * H_ * SP_ * DH_];

// ---------------- helpers ----------------
__device__ __forceinline__ unsigned smem_u32(const void* p) {
    unsigned a;
    asm("{ .reg .u64 t; cvta.to.shared.u64 t, %1; cvt.u32.u64 %0, t; }" : "=r"(a) : "l"(p));
    return a;
}
__device__ __forceinline__ void cp16(unsigned s, const void* g) {
    asm volatile("cp.async.cg.shared.global [%0], [%1], 16;" :: "r"(s), "l"(g));
}
#define CP_COMMIT() asm volatile("cp.async.commit_group;" ::: "memory")
#define CP_WAIT1()  asm volatile("cp.async.wait_group 1;" ::: "memory")
#define CP_WAIT0()  asm volatile("cp.async.wait_group 0;" ::: "memory")

#define LDM4(d0, d1, d2, d3, addr) \
    asm volatile("ldmatrix.sync.aligned.m8n8.x4.shared.b16 {%0,%1,%2,%3}, [%4];" \
        : "=r"(d0), "=r"(d1), "=r"(d2), "=r"(d3) : "r"(addr))
#define LDM4T(d0, d1, d2, d3, addr) \
    asm volatile("ldmatrix.sync.aligned.m8n8.x4.trans.shared.b16 {%0,%1,%2,%3}, [%4];" \
        : "=r"(d0), "=r"(d1), "=r"(d2), "=r"(d3) : "r"(addr))

#define MMA_BF16(c0, c1, c2, c3, a0, a1, a2, a3, b0, b1) \
    asm volatile("mma.sync.aligned.m16n8k16.row.col.f32.bf16.bf16.f32 " \
        "{%0,%1,%2,%3}, {%4,%5,%6,%7}, {%8,%9}, {%0,%1,%2,%3};" \
        : "+f"(c0), "+f"(c1), "+f"(c2), "+f"(c3) \
        : "r"(a0), "r"(a1), "r"(a2), "r"(a3), "r"(b0), "r"(b1))

__device__ __forceinline__ unsigned swz(unsigned off) {   // 64B rows (gemm tiles)
    return off ^ (((off >> 7) & 3u) << 4);
}

#define SPLIT2(v, hb, lb) do { \
    float _v = (v); \
    unsigned _u = __float_as_uint(_v); \
    hb = (_u + 0x7FFFu + ((_u >> 16) & 1u)) >> 16; \
    float _r = _v - __uint_as_float(hb << 16); \
    unsigned _w = __float_as_uint(_r); \
    lb = (_w + 0x7FFFu + ((_w >> 16) & 1u)) >> 16; \
} while (0)

// ---------------- kernel 1: LayerNorm + mix gate + bf16 split ----------------
__global__ __launch_bounds__(256) void ln_mix_kernel(
    const float* __restrict__ x, const float* __restrict__ lng,
    const float* __restrict__ lnb, const float* __restrict__ wmix,
    const float* __restrict__ bmix)
{
    int row = blockIdx.x;
    int tid = threadIdx.x;
    const float4* x4 = (const float4*)(x + (size_t)row * D_);
    float4 v0 = x4[tid];
    float4 v1 = x4[tid + 256];

    float s  = v0.x + v0.y + v0.z + v0.w + v1.x + v1.y + v1.z + v1.w;
    float s2 = v0.x*v0.x + v0.y*v0.y + v0.z*v0.z + v0.w*v0.w
             + v1.x*v1.x + v1.y*v1.y + v1.z*v1.z + v1.w*v1.w;
    #pragma unroll
    for (int o = 16; o; o >>= 1) {
        s  += __shfl_xor_sync(0xffffffffu, s,  o);
        s2 += __shfl_xor_sync(0xffffffffu, s2, o);
    }
    __shared__ float rs[8], rs2[8];
    int warp = tid >> 5, lane = tid & 31;
    if (lane == 0) { rs[warp] = s; rs2[warp] = s2; }
    __syncthreads();
    if (tid == 0) {
        float a = 0.f, b2 = 0.f;
        for (int w = 0; w < 8; w++) { a += rs[w]; b2 += rs2[w]; }
        rs[0] = a; rs2[0] = b2;
    }
    __syncthreads();
    float mu   = rs[0]  * (1.0f / D_);
    float var  = rs2[0] * (1.0f / D_) - mu * mu;
    float rstd = rsqrtf(var + EPS_);

    float xn[8];
    float xv[8] = {v0.x, v0.y, v0.z, v0.w, v1.x, v1.y, v1.z, v1.w};
    int jidx[8];
    #pragma unroll
    for (int e = 0; e < 8; e++) {
        int j = (e < 4) ? (4 * tid + e) : (1024 + 4 * tid + (e - 4));
        jidx[e] = j;
        xn[e] = (xv[e] - mu) * rstd * lng[j] + lnb[j];
    }
    unsigned hb[8], lb[8];
    #pragma unroll
    for (int e = 0; e < 8; e++) SPLIT2(xn[e], hb[e], lb[e]);
    size_t base = (size_t)row * D_;
    *(uint2*)(g_A1h + base + 4 * tid) =
        make_uint2(hb[0] | (hb[1] << 16), hb[2] | (hb[3] << 16));
    *(uint2*)(g_A1l + base + 4 * tid) =
        make_uint2(lb[0] | (lb[1] << 16), lb[2] | (lb[3] << 16));
    *(uint2*)(g_A1h + base + 1024 + 4 * tid) =
        make_uint2(hb[4] | (hb[5] << 16), hb[6] | (hb[7] << 16));
    *(uint2*)(g_A1l + base + 1024 + 4 * tid) =
        make_uint2(lb[4] | (lb[5] << 16), lb[6] | (lb[7] << 16));

    float acc[16];
    #pragma unroll
    for (int h = 0; h < 16; h++) acc[h] = 0.f;
    #pragma unroll
    for (int e = 0; e < 8; e++) {
        const float4* wm = (const float4*)(wmix + (size_t)jidx[e] * H_);
        float4 a0 = wm[0], a1 = wm[1], a2 = wm[2], a3 = wm[3];
        float xe = xn[e];
        acc[0]  += xe * a0.x; acc[1]  += xe * a0.y; acc[2]  += xe * a0.z; acc[3]  += xe * a0.w;
        acc[4]  += xe * a1.x; acc[5]  += xe * a1.y; acc[6]  += xe * a1.z; acc[7]  += xe * a1.w;
        acc[8]  += xe * a2.x; acc[9]  += xe * a2.y; acc[10] += xe * a2.z; acc[11] += xe * a2.w;
        acc[12] += xe * a3.x; acc[13] += xe * a3.y; acc[14] += xe * a3.z; acc[15] += xe * a3.w;
    }
    #pragma unroll
    for (int h = 0; h < 16; h++) {
        #pragma unroll
        for (int o = 16; o; o >>= 1) acc[h] += __shfl_xor_sync(0xffffffffu, acc[h], o);
    }
    __shared__ float wsum[8][16];
    if (lane == 0) {
        #pragma unroll
        for (int h = 0; h < 16; h++) wsum[warp][h] = acc[h];
    }
    __syncthreads();
    if (tid < 16) {
        float t = 0.f;
        #pragma unroll
        for (int w = 0; w < 8; w++) t += wsum[w][tid];
        t += bmix[tid];
        g_mix[(size_t)row * H_ + tid] = 1.0f / (1.0f + expf(-t));
    }
}

// ---------------- transpose + split weights ----------------
template <int WHICH>
__global__ __launch_bounds__(256) void transconv_kernel(const float* __restrict__ src)
{
    const int Rows = D_;
    const int Cols = (WHICH == 0) ? 3 * D_ : D_;
    unsigned short* __restrict__ dhi = (WHICH == 0) ? g_Bqh : g_Boh;
    unsigned short* __restrict__ dlo = (WHICH == 0) ? g_Bql : g_Bol;

    __shared__ float tile[32][33];
    int bx = blockIdx.x * 32;
    int by = blockIdx.y * 32;
    int tx = threadIdx.x & 31, ty = threadIdx.x >> 5;
    #pragma unroll
    for (int i = 0; i < 32; i += 8)
        tile[ty + i][tx] = src[(size_t)(by + ty + i) * Cols + bx + tx];
    __syncthreads();
    #pragma unroll
    for (int i = 0; i < 32; i += 8) {
        unsigned h, l;
        SPLIT2(tile[tx][ty + i], h, l);
        size_t o = (size_t)(bx + ty + i) * Rows + by + tx;
        dhi[o] = (unsigned short)h;
        dlo[o] = (unsigned short)l;
    }
}

// ---------------- pmem prepend (split bf16) ----------------
__global__ __launch_bounds__(256) void pmem_kernel(const float* __restrict__ pmem)
{
    int i = blockIdx.x * 256 + threadIdx.x;
    int b = i >> 15;
    int rem = i & 32767;
    int h = rem >> 11;
    int jd = rem & 2047;
    int j = jd >> 7, d = jd & 127;
    size_t dst = (((size_t)(b * H_ + h)) * SP_ + j) * DH_ + d;
    unsigned kh, kl, vh, vl;
    SPLIT2(pmem[rem], kh, kl);
    SPLIT2(pmem[32768 + rem], vh, vl);
    g_kh[dst] = (unsigned short)kh;
    g_kl[dst] = (unsigned short)kl;
    g_vh[dst] = (unsigned short)vh;
    g_vl[dst] = (unsigned short)vl;
}

// ---------------- HMMA bf16x3 GEMM: 128x128x32 tile, cp.async 3-stage --------
#define BK_ 32
#define NCH (D_ / BK_)
#define STG 32768
#define GEMM_SMEM (3 * STG + 1024)

#define LOAD_STAGE(st, k0) do { \
    unsigned _sp = sbase + (st) * STG; \
    size_t _ga0 = (size_t)(m0 + r0c) * D_ + (k0) + k0c * 8; \
    size_t _ga1 = (size_t)(m0 + r1c) * D_ + (k0) + k0c * 8; \
    size_t _gb0 = (size_t)(n0 + r0c) * D_ + (k0) + k0c * 8; \
    size_t _gb1 = (size_t)(n0 + r1c) * D_ + (k0) + k0c * 8; \
    cp16(_sp + so0,         Ah + _ga0);  cp16(_sp + so1,         Ah + _ga1); \
    cp16(_sp + 8192 + so0,  Al + _ga0);  cp16(_sp + 8192 + so1,  Al + _ga1); \
    cp16(_sp + 16384 + so0, Bh + _gb0);  cp16(_sp + 16384 + so1, Bh + _gb1); \
    cp16(_sp + 24576 + so0, Bl + _gb0);  cp16(_sp + 24576 + so1, Bl + _gb1); \
} while (0)

template <int MODE>
__global__ __launch_bounds__(256, 1) void gemm_kernel(
    const float* __restrict__ vres, const float* __restrict__ bout,
    float* __restrict__ Cout)
{
    extern __shared__ char dynsm[];
    unsigned braw = smem_u32(dynsm);
    unsigned sbase = (braw + 1023) & ~1023u;

    int tid = threadIdx.x;
    int lane = tid & 31, wid = tid >> 5;
    int warp_m = wid & 3, warp_n = wid >> 2;
    int m0 = blockIdx.y * 128, n0 = blockIdx.x * 128;
    int wm = warp_m * 32, wn = warp_n * 64;

    const unsigned short* Ah = (MODE == 0) ? g_A1h : g_A2h;
    const unsigned short* Al = (MODE == 0) ? g_A1l : g_A2l;
    const unsigned short* Bh = (MODE == 0) ? g_Bqh : g_Boh;
    const unsigned short* Bl = (MODE == 0) ? g_Bql : g_Bol;

    int r0c = tid >> 2, k0c = tid & 3;
    int r1c = (tid + 256) >> 2;
    unsigned so0 = swz((unsigned)(r0c * 64 + k0c * 16));
    unsigned so1 = swz((unsigned)(r1c * 64 + k0c * 16));

    int t4 = lane >> 3, lr = lane & 7;
    int a_row = ((t4 & 1) << 3) + lr;
    int a_cb  = (t4 >> 1) << 4;
    int b_row = ((t4 >> 1) << 3) + lr;
    int b_cb  = (t4 & 1) << 4;

    float acc[2][8][4];
    #pragma unroll
    for (int i = 0; i < 2; i++)
        #pragma unroll
        for (int j = 0; j < 8; j++)
            #pragma unroll
            for (int q = 0; q < 4; q++) acc[i][j][q] = 0.f;

    LOAD_STAGE(0, 0); CP_COMMIT();
    LOAD_STAGE(1, BK_); CP_COMMIT();

    #pragma unroll 1
    for (int c = 0; c < NCH; c++) {
        if (c + 2 < NCH) CP_WAIT1(); else CP_WAIT0();
        __syncthreads();
        if (c + 2 < NCH) { LOAD_STAGE((c + 2) % 3, (c + 2) * BK_); CP_COMMIT(); }

        unsigned sp = sbase + (c % 3) * STG;
        unsigned sAh = sp, sAl = sp + 8192, sBh = sp + 16384, sBl = sp + 24576;

        #pragma unroll
        for (int ks = 0; ks < 2; ks++) {
            unsigned bh[8][2], bl[8][2];
            #pragma unroll
            for (int np = 0; np < 4; np++) {
                unsigned off = swz((unsigned)((wn + np * 16 + b_row) * 64 + ks * 32 + b_cb));
                LDM4(bh[2*np][0], bh[2*np][1], bh[2*np+1][0], bh[2*np+1][1], sBh + off);
                LDM4(bl[2*np][0], bl[2*np][1], bl[2*np+1][0], bl[2*np+1][1], sBl + off);
            }
            #pragma unroll
            for (int mt = 0; mt < 2; mt++) {
                unsigned ah0, ah1, ah2, ah3, al0, al1, al2, al3;
                unsigned off = swz((unsigned)((wm + mt * 16 + a_row) * 64 + ks * 32 + a_cb));
                LDM4(ah0, ah1, ah2, ah3, sAh + off);
                LDM4(al0, al1, al2, al3, sAl + off);
                #pragma unroll
                for (int nt = 0; nt < 8; nt++) {
                    MMA_BF16(acc[mt][nt][0], acc[mt][nt][1], acc[mt][nt][2], acc[mt][nt][3],
                             ah0, ah1, ah2, ah3, bh[nt][0], bh[nt][1]);
                    MMA_BF16(acc[mt][nt][0], acc[mt][nt][1], acc[mt][nt][2], acc[mt][nt][3],
                             ah0, ah1, ah2, ah3, bl[nt][0], bl[nt][1]);
                    MMA_BF16(acc[mt][nt][0], acc[mt][nt][1], acc[mt][nt][2], acc[mt][nt][3],
                             al0, al1, al2, al3, bh[nt][0], bh[nt][1]);
                }
            }
        }
        __syncthreads();
    }

    // ---- epilogue ----
    #pragma unroll
    for (int mt = 0; mt < 2; mt++) {
        #pragma unroll
        for (int nt = 0; nt < 8; nt++) {
            int mrow0 = m0 + wm + mt * 16 + (lane >> 2);
            int n     = n0 + wn + nt * 8 + 2 * (lane & 3);
            #pragma unroll
            for (int half = 0; half < 2; half++) {
                int m = mrow0 + half * 8;
                float va = acc[mt][nt][2 * half];
                float vb = acc[mt][nt][2 * half + 1];
                int b = m >> 11, sg = m & 2047;
                if (MODE == 0) {
                    int seg = n >> 11;
                    int nn = n & 2047;
                    int hd = nn >> 7, d = nn & 127;
                    if (seg == 2) {
                        float mx = g_mix[(size_t)m * H_ + hd];
                        float2 vr = *(const float2*)(vres + (((size_t)(b * H_ + hd)) * S_ + sg) * DH_ + d);
                        float om = 1.0f - mx;
                        va = va * om + vr.x * mx;
                        vb = vb * om + vr.y * mx;
                    }
                    unsigned sh0, sl0, sh1, sl1;
                    SPLIT2(va, sh0, sl0);
                    SPLIT2(vb, sh1, sl1);
                    if (seg == 0) {
                        size_t idx = (((size_t)(b * H_ + hd)) * S_ + sg) * DH_ + d;
                        *(unsigned*)(g_qh + idx) = sh0 | (sh1 << 16);
                        *(unsigned*)(g_ql + idx) = sl0 | (sl1 << 16);
                    } else if (seg == 1) {
                        size_t idx = (((size_t)(b * H_ + hd)) * SP_ + P_ + sg) * DH_ + d;
                        *(unsigned*)(g_kh + idx) = sh0 | (sh1 << 16);
                        *(unsigned*)(g_kl + idx) = sl0 | (sl1 << 16);
                    } else {
                        size_t idx = (((size_t)(b * H_ + hd)) * SP_ + P_ + sg) * DH_ + d;
                        *(unsigned*)(g_vh + idx) = sh0 | (sh1 << 16);
                        *(unsigned*)(g_vl + idx) = sl0 | (sl1 << 16);
                    }
                } else {
                    *(float2*)(Cout + (size_t)m * D_ + n) =
                        make_float2(va + bout[n], vb + bout[n + 1]);
                }
            }
        }
    }
}

// ---------------- flash attention v2: HMMA bf16x3 for QK^T and PV ------------
// smem layout (byte offsets from 1KB-aligned base):
#define AQH 0
#define AQL 16384
#define AKV0 32768        // 2 KV buffers x 64KB (Kh|Kl|Vh|Vl each 16KB)
#define APH 163840
#define APL 172032
#define ASS 180224        // float [64][65]
#define AMS 196864
#define ALS 197120
#define ACS 197376
#define ATTN_SMEM (197632 + 1024)

#define LOAD_KV(bufi, j0v) do { \
    unsigned _kb = sbase + AKV0 + (bufi) * 65536; \
    size_t _gk = (size_t)bh * SP_; \
    _Pragma("unroll") \
    for (int _i = 0; _i < 4; _i++) { \
        int _ci = tid + _i * 256; \
        int _r = _ci >> 4, _c = _ci & 15; \
        int _jg = (j0v) + _r; if (_jg > SP_ - 1) _jg = SP_ - 1; \
        unsigned _sw = (unsigned)(_c ^ (_r & 7)); \
        unsigned _d = _kb + _r * 256 + _sw * 16; \
        size_t _go = (_gk + _jg) * DH_ + _c * 8; \
        cp16(_d,         g_kh + _go); \
        cp16(_d + 16384, g_kl + _go); \
        cp16(_d + 32768, g_vh + _go); \
        cp16(_d + 49152, g_vl + _go); \
    } \
} while (0)

__global__ __launch_bounds__(256, 1) void attn_kernel()
{
    extern __shared__ char dynsm2[];
    unsigned braw = smem_u32(dynsm2);
    unsigned sbase = (braw + 1023) & ~1023u;
    char* smc = dynsm2 + (sbase - braw);

    int tid = threadIdx.x;
    int lane = tid & 31, wid = tid >> 5;
    int qt = blockIdx.x, h = blockIdx.y, b = blockIdx.z;
    int bh = b * H_ + h;
    int qbase = qt * 64;

    float* Ss  = (float*)(smc + ASS);
    float* msm = (float*)(smc + AMS);
    float* lsm = (float*)(smc + ALS);
    float* csm = (float*)(smc + ACS);

    // ---- load Q split (group 0, together with KV tile 0) ----
    {
        size_t gq = (size_t)bh * S_ + qbase;
        #pragma unroll
        for (int i = 0; i < 4; i++) {
            int ci = tid + i * 256;
            int r = ci >> 4, c = ci & 15;
            unsigned sw = (unsigned)(c ^ (r & 7));
            unsigned dst = sbase + AQH + r * 256 + sw * 16;
            cp16(dst,         g_qh + (gq + r) * DH_ + c * 8);
            cp16(dst + 16384, g_ql + (gq + r) * DH_ + c * 8);
        }
    }
    LOAD_KV(0, 0);
    CP_COMMIT();

    if (tid < 64) { msm[tid] = -INFINITY; lsm[tid] = 0.f; }

    float oacc[2][4][4];
    #pragma unroll
    for (int i = 0; i < 2; i++)
        #pragma unroll
        for (int j = 0; j < 4; j++)
            #pragma unroll
            for (int q = 0; q < 4; q++) oacc[i][j][q] = 0.f;

    const float scale = 0.08838834764831845f;
    int ntiles = (P_ + qbase + 64 + 63) >> 6;

    int t4 = lane >> 3, lr = lane & 7;
    int a_row  = ((t4 & 1) << 3) + lr;
    int a_csel = t4 >> 1;
    int b_row  = ((t4 >> 1) << 3) + lr;
    int b_csel = t4 & 1;
    int r_b = lane >> 2, c_b = (lane & 3) * 2;

    int wmS = (wid & 1) * 32, wnS = (wid >> 1) * 16;
    int wmO = wmS,            wnO = (wid >> 1) * 32;

    #pragma unroll 1
    for (int t = 0; t < ntiles; t++) {
        int j0 = t << 6;
        if (t + 1 < ntiles) { LOAD_KV((t + 1) & 1, (t + 1) * 64); CP_COMMIT(); CP_WAIT1(); }
        else CP_WAIT0();
        __syncthreads();

        unsigned kvb = sbase + AKV0 + (t & 1) * 65536;
        unsigned sKh = kvb, sKl = kvb + 16384, sVh = kvb + 32768, sVl = kvb + 49152;

        // ---- S = Q K^T (3-term bf16) ----
        float sacc[2][2][4];
        #pragma unroll
        for (int i = 0; i < 2; i++)
            #pragma unroll
            for (int j = 0; j < 2; j++)
                #pragma unroll
                for (int q = 0; q < 4; q++) sacc[i][j][q] = 0.f;

        #pragma unroll
        for (int ks = 0; ks < 8; ks++) {
            unsigned kh[2][2], kl[2][2];
            {
                unsigned row = (unsigned)(wnS + b_row);
                unsigned ch = (unsigned)(ks * 2 + b_csel);
                unsigned addr = sKh + row * 256 + (ch ^ (row & 7)) * 16;
                LDM4(kh[0][0], kh[0][1], kh[1][0], kh[1][1], addr);
                LDM4(kl[0][0], kl[0][1], kl[1][0], kl[1][1], addr + 16384);
            }
            #pragma unroll
            for (int mt = 0; mt < 2; mt++) {
                unsigned row = (unsigned)(wmS + mt * 16 + a_row);
                unsigned ch = (unsigned)(ks * 2 + a_csel);
                unsigned addr = sbase + AQH + row * 256 + (ch ^ (row & 7)) * 16;
                unsigned qh0, qh1, qh2, qh3, ql0, ql1, ql2, ql3;
                LDM4(qh0, qh1, qh2, qh3, addr);
                LDM4(ql0, ql1, ql2, ql3, addr + 16384);
                #pragma unroll
                for (int n8 = 0; n8 < 2; n8++) {
                    MMA_BF16(sacc[mt][n8][0], sacc[mt][n8][1], sacc[mt][n8][2], sacc[mt][n8][3],
                             qh0, qh1, qh2, qh3, kh[n8][0], kh[n8][1]);
                    MMA_BF16(sacc[mt][n8][0], sacc[mt][n8][1], sacc[mt][n8][2], sacc[mt][n8][3],
                             qh0, qh1, qh2, qh3, kl[n8][0], kl[n8][1]);
                    MMA_BF16(sacc[mt][n8][0], sacc[mt][n8][1], sacc[mt][n8][2], sacc[mt][n8][3],
                             ql0, ql1, ql2, ql3, kh[n8][0], kh[n8][1]);
                }
            }
        }
        // scale + mask -> Ss
        #pragma unroll
        for (int mt = 0; mt < 2; mt++) {
            #pragma unroll
            for (int n8 = 0; n8 < 2; n8++) {
                int r0 = wmS + mt * 16 + r_b;
                int c0 = wnS + n8 * 8 + c_b;
                #pragma unroll
                for (int half = 0; half < 2; half++) {
                    int r = r0 + half * 8;
                    int ig = qbase + r;
                    #pragma unroll
                    for (int e = 0; e < 2; e++) {
                        int jg = j0 + c0 + e;
                        float sv = sacc[mt][n8][half * 2 + e] * scale;
                        if (jg >= P_ && (jg - P_) > ig) sv = -1e30f;
                        Ss[r * 65 + c0 + e] = sv;
                    }
                }
            }
        }
        __syncthreads();

        // ---- online softmax; write P split bf16 ----
        {
            int row = tid >> 2, sub = tid & 3;
            float mloc = -1e30f;
            #pragma unroll
            for (int e = 0; e < 16; e++) mloc = fmaxf(mloc, Ss[row * 65 + sub * 16 + e]);
            mloc = fmaxf(mloc, __shfl_xor_sync(0xffffffffu, mloc, 1));
            mloc = fmaxf(mloc, __shfl_xor_sync(0xffffffffu, mloc, 2));
            float mold = msm[row];
            float mnew = fmaxf(mold, mloc);
            float corr = __expf(mold - mnew);
            float ps = 0.f;
            #pragma unroll
            for (int e2 = 0; e2 < 8; e2++) {
                int c = sub * 16 + e2 * 2;
                float p0 = __expf(Ss[row * 65 + c] - mnew);
                float p1 = __expf(Ss[row * 65 + c + 1] - mnew);
                ps += p0 + p1;
                unsigned h0, l0, h1, l1;
                SPLIT2(p0, h0, l0);
                SPLIT2(p1, h1, l1);
                unsigned ch = (unsigned)(c >> 3);
                unsigned bo = (unsigned)row * 128 + (ch ^ ((unsigned)row & 7)) * 16 + (c & 7) * 2;
                *(unsigned*)(smc + APH + bo) = h0 | (h1 << 16);
                *(unsigned*)(smc + APL + bo) = l0 | (l1 << 16);
            }
            ps += __shfl_xor_sync(0xffffffffu, ps, 1);
            ps += __shfl_xor_sync(0xffffffffu, ps, 2);
            if (sub == 0) { msm[row] = mnew; lsm[row] = lsm[row] * corr + ps; csm[row] = corr; }
        }
        __syncthreads();

        // ---- O = O*corr + P V (3-term bf16) ----
        #pragma unroll
        for (int mt = 0; mt < 2; mt++) {
            float cr0 = csm[wmO + mt * 16 + r_b];
            float cr1 = csm[wmO + mt * 16 + r_b + 8];
            #pragma unroll
            for (int n8 = 0; n8 < 4; n8++) {
                oacc[mt][n8][0] *= cr0; oacc[mt][n8][1] *= cr0;
                oacc[mt][n8][2] *= cr1; oacc[mt][n8][3] *= cr1;
            }
        }
        #pragma unroll
        for (int ks = 0; ks < 4; ks++) {
            unsigned vh[4][2], vl[4][2];
            {
                unsigned krow = (unsigned)(ks * 16 + (lane & 15));
                unsigned chx = (unsigned)(lane >> 4);
                #pragma unroll
                for (int p = 0; p < 2; p++) {
                    unsigned ch = (unsigned)((wnO + p * 16) >> 3) + chx;
                    unsigned addr = sVh + krow * 256 + (ch ^ (krow & 7)) * 16;
                    LDM4T(vh[2*p][0], vh[2*p][1], vh[2*p+1][0], vh[2*p+1][1], addr);
                    LDM4T(vl[2*p][0], vl[2*p][1], vl[2*p+1][0], vl[2*p+1][1], addr + 16384);
                }
            }
            #pragma unroll
            for (int mt = 0; mt < 2; mt++) {
                unsigned row = (unsigned)(wmO + mt * 16 + a_row);
                unsigned ch = (unsigned)(ks * 2 + a_csel);
                unsigned bo = row * 128 + (ch ^ (row & 7)) * 16;
                unsigned ph0, ph1, ph2, ph3, pl0, pl1, pl2, pl3;
                LDM4(ph0, ph1, ph2, ph3, sbase + APH + bo);
                LDM4(pl0, pl1, pl2, pl3, sbase + APL + bo);
                #pragma unroll
                for (int n8 = 0; n8 < 4; n8++) {
                    MMA_BF16(oacc[mt][n8][0], oacc[mt][n8][1], oacc[mt][n8][2], oacc[mt][n8][3],
                             ph0, ph1, ph2, ph3, vh[n8][0], vh[n8][1]);
                    MMA_BF16(oacc[mt][n8][0], oacc[mt][n8][1], oacc[mt][n8][2], oacc[mt][n8][3],
                             ph0, ph1, ph2, ph3, vl[n8][0], vl[n8][1]);
                    MMA_BF16(oacc[mt][n8][0], oacc[mt][n8][1], oacc[mt][n8][2], oacc[mt][n8][3],
                             pl0, pl1, pl2, pl3, vh[n8][0], vh[n8][1]);
                }
            }
        }
        __syncthreads();
    }

    // ---- final: scale by 1/l, split, store ----
    #pragma unroll
    for (int mt = 0; mt < 2; mt++) {
        int r0 = wmO + mt * 16 + r_b;
        float li0 = 1.0f / lsm[r0];
        float li1 = 1.0f / lsm[r0 + 8];
        size_t ro0 = ((size_t)(b * S_ + qbase + r0)) * D_ + h * DH_;
        size_t ro1 = ((size_t)(b * S_ + qbase + r0 + 8)) * D_ + h * DH_;
        #pragma unroll
        for (int n8 = 0; n8 < 4; n8++) {
            int c = wnO + n8 * 8 + c_b;
            unsigned h0, l0, h1, l1;
            SPLIT2(oacc[mt][n8][0] * li0, h0, l0);
            SPLIT2(oacc[mt][n8][1] * li0, h1, l1);
            *(unsigned*)(g_A2h + ro0 + c) = h0 | (h1 << 16);
            *(unsigned*)(g_A2l + ro0 + c) = l0 | (l1 << 16);
            SPLIT2(oacc[mt][n8][2] * li1, h0, l0);
            SPLIT2(oacc[mt][n8][3] * li1, h1, l1);
            *(unsigned*)(g_A2h + ro1 + c) = h0 | (h1 << 16);
            *(unsigned*)(g_A2l + ro1 + c) = l0 | (l1 << 16);
        }
    }
}

// ---------------- launch ------------------------------------------------------
extern "C" void kernel_launch(void* const* d_in, const int* in_sizes, int n_in,
                              void* d_out, int out_size)
{
    const float* x    = (const float*)d_in[0];
    const float* vres = (const float*)d_in[1];
    const float* lng  = (const float*)d_in[2];
    const float* lnb  = (const float*)d_in[3];
    const float* wqkv = (const float*)d_in[4];
    const float* wout = (const float*)d_in[5];
    const float* bout = (const float*)d_in[6];
    const float* wmix = (const float*)d_in[7];
    const float* bmix = (const float*)d_in[8];
    const float* pmem = (const float*)d_in[9];
    float* out = (float*)d_out;

    cudaFuncSetAttribute(attn_kernel, cudaFuncAttributeMaxDynamicSharedMemorySize, ATTN_SMEM);
    cudaFuncSetAttribute(gemm_kernel<0>, cudaFuncAttributeMaxDynamicSharedMemorySize, GEMM_SMEM);
    cudaFuncSetAttribute(gemm_kernel<1>, cudaFuncAttributeMaxDynamicSharedMemorySize, GEMM_SMEM);

    ln_mix_kernel<<<BS_, 256>>>(x, lng, lnb, wmix, bmix);
    transconv_kernel<0><<<dim3(3 * D_ / 32, D_ / 32), 256>>>(wqkv);
    transconv_kernel<1><<<dim3(D_ / 32, D_ / 32), 256>>>(wout);
    pmem_kernel<<<256, 256>>>(pmem);
    gemm_kernel<0><<<dim3(3 * D_ / 128, BS_ / 128), 256, GEMM_SMEM>>>(vres, nullptr, nullptr);
    attn_kernel<<<dim3(S_ / 64, H_, B_), 256, ATTN_SMEM>>>();
    gemm_kernel<1><<<dim3(D_ / 128, BS_ / 128), 256, GEMM_SMEM>>>(nullptr, bout, out);
}

// round 10
// speedup vs baseline: 3.0598x; 1.2220x over previous
// Round 10: resubmission of round-9 source (round 9 hit the GB300 broker
// infra failure twice and never compiled/ran). Under test: FA2 attention
// (Q128 tile, register-resident P, C-frag->A-frag reuse) + GEMM BK=64.
#include <cuda_runtime.h>
#include <math.h>

#define B_   2
#define S_   2048
#define D_   2048
#define H_   16
#define DH_  128
#define P_   16
#define SP_  2064
#define BS_  4096
#define EPS_ 1e-5f

// ---------------- static scratch ----------------
__device__ __align__(16) unsigned short g_A1h[BS_ * D_];
__device__ __align__(16) unsigned short g_A1l[BS_ * D_];
__device__ __align__(16) unsigned short g_Bqh[3 * D_ * D_];
__device__ __align__(16) unsigned short g_Bql[3 * D_ * D_];
__device__ __align__(16) unsigned short g_Boh[D_ * D_];
__device__ __align__(16) unsigned short g_Bol[D_ * D_];
__device__ __align__(16) unsigned short g_A2h[BS_ * D_];
__device__ __align__(16) unsigned short g_A2l[BS_ * D_];
__device__ float g_mix[BS_ * H_];
__device__ __align__(16) unsigned short g_qh[B_ * H_ * S_  * DH_];
__device__ __align__(16) unsigned short g_ql[B_ * H_ * S_  * DH_];
__device__ __align__(16) unsigned short g_kh[B_ * H_ * SP_ * DH_];
__device__ __align__(16) unsigned short g_kl[B_ * H_ * SP_ * DH_];
__device__ __align__(16) unsigned short g_vh[B_ * H_ * SP_ * DH_];
__device__ __align__(16) unsigned short g_vl[B_ * H_ * SP_ * DH_];

// ---------------- helpers ----------------
__device__ __forceinline__ unsigned smem_u32(const void* p) {
    unsigned a;
    asm("{ .reg .u64 t; cvta.to.shared.u64 t, %1; cvt.u32.u64 %0, t; }" : "=r"(a) : "l"(p));
    return a;
}
__device__ __forceinline__ void cp16(unsigned s, const void* g) {
    asm volatile("cp.async.cg.shared.global [%0], [%1], 16;" :: "r"(s), "l"(g));
}
#define CP_COMMIT() asm volatile("cp.async.commit_group;" ::: "memory")
#define CP_WAIT1()  asm volatile("cp.async.wait_group 1;" ::: "memory")
#define CP_WAIT0()  asm volatile("cp.async.wait_group 0;" ::: "memory")

#define LDM4(d0, d1, d2, d3, addr) \
    asm volatile("ldmatrix.sync.aligned.m8n8.x4.shared.b16 {%0,%1,%2,%3}, [%4];" \
        : "=r"(d0), "=r"(d1), "=r"(d2), "=r"(d3) : "r"(addr))
#define LDM4T(d0, d1, d2, d3, addr) \
    asm volatile("ldmatrix.sync.aligned.m8n8.x4.trans.shared.b16 {%0,%1,%2,%3}, [%4];" \
        : "=r"(d0), "=r"(d1), "=r"(d2), "=r"(d3) : "r"(addr))

#define MMA_BF16(c0, c1, c2, c3, a0, a1, a2, a3, b0, b1) \
    asm volatile("mma.sync.aligned.m16n8k16.row.col.f32.bf16.bf16.f32 " \
        "{%0,%1,%2,%3}, {%4,%5,%6,%7}, {%8,%9}, {%0,%1,%2,%3};" \
        : "+f"(c0), "+f"(c1), "+f"(c2), "+f"(c3) \
        : "r"(a0), "r"(a1), "r"(a2), "r"(a3), "r"(b0), "r"(b1))

// bf16 split, RNE, scalar
#define SPLIT2(v, hb, lb) do { \
    float _v = (v); \
    unsigned _u = __float_as_uint(_v); \
    hb = (_u + 0x7FFFu + ((_u >> 16) & 1u)) >> 16; \
    float _r = _v - __uint_as_float(hb << 16); \
    unsigned _w = __float_as_uint(_r); \
    lb = (_w + 0x7FFFu + ((_w >> 16) & 1u)) >> 16; \
} while (0)

// paired split via cvt.rn.bf16x2: hpack = {lo16 = bf16(v0), hi16 = bf16(v1)}
#define SPLIT2X2(v0, v1, hpack, lpack) do { \
    float _a = (v0), _b = (v1); \
    asm("cvt.rn.bf16x2.f32 %0, %1, %2;" : "=r"(hpack) : "f"(_b), "f"(_a)); \
    float _r0 = _a - __uint_as_float((hpack) << 16); \
    float _r1 = _b - __uint_as_float((hpack) & 0xFFFF0000u); \
    asm("cvt.rn.bf16x2.f32 %0, %1, %2;" : "=r"(lpack) : "f"(_r1), "f"(_r0)); \
} while (0)

// ---------------- kernel 1: LayerNorm + mix gate + bf16 split ----------------
__global__ __launch_bounds__(256) void ln_mix_kernel(
    const float* __restrict__ x, const float* __restrict__ lng,
    const float* __restrict__ lnb, const float* __restrict__ wmix,
    const float* __restrict__ bmix)
{
    int row = blockIdx.x;
    int tid = threadIdx.x;
    const float4* x4 = (const float4*)(x + (size_t)row * D_);
    float4 v0 = x4[tid];
    float4 v1 = x4[tid + 256];

    float s  = v0.x + v0.y + v0.z + v0.w + v1.x + v1.y + v1.z + v1.w;
    float s2 = v0.x*v0.x + v0.y*v0.y + v0.z*v0.z + v0.w*v0.w
             + v1.x*v1.x + v1.y*v1.y + v1.z*v1.z + v1.w*v1.w;
    #pragma unroll
    for (int o = 16; o; o >>= 1) {
        s  += __shfl_xor_sync(0xffffffffu, s,  o);
        s2 += __shfl_xor_sync(0xffffffffu, s2, o);
    }
    __shared__ float rs[8], rs2[8];
    int warp = tid >> 5, lane = tid & 31;
    if (lane == 0) { rs[warp] = s; rs2[warp] = s2; }
    __syncthreads();
    if (tid == 0) {
        float a = 0.f, b2 = 0.f;
        for (int w = 0; w < 8; w++) { a += rs[w]; b2 += rs2[w]; }
        rs[0] = a; rs2[0] = b2;
    }
    __syncthreads();
    float mu   = rs[0]  * (1.0f / D_);
    float var  = rs2[0] * (1.0f / D_) - mu * mu;
    float rstd = rsqrtf(var + EPS_);

    float xn[8];
    float xv[8] = {v0.x, v0.y, v0.z, v0.w, v1.x, v1.y, v1.z, v1.w};
    int jidx[8];
    #pragma unroll
    for (int e = 0; e < 8; e++) {
        int j = (e < 4) ? (4 * tid + e) : (1024 + 4 * tid + (e - 4));
        jidx[e] = j;
        xn[e] = (xv[e] - mu) * rstd * lng[j] + lnb[j];
    }
    unsigned hb[8], lb[8];
    #pragma unroll
    for (int e = 0; e < 8; e++) SPLIT2(xn[e], hb[e], lb[e]);
    size_t base = (size_t)row * D_;
    *(uint2*)(g_A1h + base + 4 * tid) =
        make_uint2(hb[0] | (hb[1] << 16), hb[2] | (hb[3] << 16));
    *(uint2*)(g_A1l + base + 4 * tid) =
        make_uint2(lb[0] | (lb[1] << 16), lb[2] | (lb[3] << 16));
    *(uint2*)(g_A1h + base + 1024 + 4 * tid) =
        make_uint2(hb[4] | (hb[5] << 16), hb[6] | (hb[7] << 16));
    *(uint2*)(g_A1l + base + 1024 + 4 * tid) =
        make_uint2(lb[4] | (lb[5] << 16), lb[6] | (lb[7] << 16));

    float acc[16];
    #pragma unroll
    for (int h = 0; h < 16; h++) acc[h] = 0.f;
    #pragma unroll
    for (int e = 0; e < 8; e++) {
        const float4* wm = (const float4*)(wmix + (size_t)jidx[e] * H_);
        float4 a0 = wm[0], a1 = wm[1], a2 = wm[2], a3 = wm[3];
        float xe = xn[e];
        acc[0]  += xe * a0.x; acc[1]  += xe * a0.y; acc[2]  += xe * a0.z; acc[3]  += xe * a0.w;
        acc[4]  += xe * a1.x; acc[5]  += xe * a1.y; acc[6]  += xe * a1.z; acc[7]  += xe * a1.w;
        acc[8]  += xe * a2.x; acc[9]  += xe * a2.y; acc[10] += xe * a2.z; acc[11] += xe * a2.w;
        acc[12] += xe * a3.x; acc[13] += xe * a3.y; acc[14] += xe * a3.z; acc[15] += xe * a3.w;
    }
    #pragma unroll
    for (int h = 0; h < 16; h++) {
        #pragma unroll
        for (int o = 16; o; o >>= 1) acc[h] += __shfl_xor_sync(0xffffffffu, acc[h], o);
    }
    __shared__ float wsum[8][16];
    if (lane == 0) {
        #pragma unroll
        for (int h = 0; h < 16; h++) wsum[warp][h] = acc[h];
    }
    __syncthreads();
    if (tid < 16) {
        float t = 0.f;
        #pragma unroll
        for (int w = 0; w < 8; w++) t += wsum[w][tid];
        t += bmix[tid];
        g_mix[(size_t)row * H_ + tid] = 1.0f / (1.0f + expf(-t));
    }
}

// ---------------- transpose + split weights ----------------
template <int WHICH>
__global__ __launch_bounds__(256) void transconv_kernel(const float* __restrict__ src)
{
    const int Rows = D_;
    const int Cols = (WHICH == 0) ? 3 * D_ : D_;
    unsigned short* __restrict__ dhi = (WHICH == 0) ? g_Bqh : g_Boh;
    unsigned short* __restrict__ dlo = (WHICH == 0) ? g_Bql : g_Bol;

    __shared__ float tile[32][33];
    int bx = blockIdx.x * 32;
    int by = blockIdx.y * 32;
    int tx = threadIdx.x & 31, ty = threadIdx.x >> 5;
    #pragma unroll
    for (int i = 0; i < 32; i += 8)
        tile[ty + i][tx] = src[(size_t)(by + ty + i) * Cols + bx + tx];
    __syncthreads();
    #pragma unroll
    for (int i = 0; i < 32; i += 8) {
        unsigned h, l;
        SPLIT2(tile[tx][ty + i], h, l);
        size_t o = (size_t)(bx + ty + i) * Rows + by + tx;
        dhi[o] = (unsigned short)h;
        dlo[o] = (unsigned short)l;
    }
}

// ---------------- pmem prepend (split bf16) ----------------
__global__ __launch_bounds__(256) void pmem_kernel(const float* __restrict__ pmem)
{
    int i = blockIdx.x * 256 + threadIdx.x;
    int b = i >> 15;
    int rem = i & 32767;
    int h = rem >> 11;
    int jd = rem & 2047;
    int j = jd >> 7, d = jd & 127;
    size_t dst = (((size_t)(b * H_ + h)) * SP_ + j) * DH_ + d;
    unsigned kh, kl, vh, vl;
    SPLIT2(pmem[rem], kh, kl);
    SPLIT2(pmem[32768 + rem], vh, vl);
    g_kh[dst] = (unsigned short)kh;
    g_kl[dst] = (unsigned short)kl;
    g_vh[dst] = (unsigned short)vh;
    g_vl[dst] = (unsigned short)vl;
}

// ---------------- HMMA bf16x3 GEMM: 128x128x64 chunks, cp.async 3-stage ------
#define BK_ 64
#define NCH (D_ / BK_)          // 32 chunks
#define STG 65536               // Ah 16K | Al 16K | Bh 16K | Bl 16K
#define GEMM_SMEM (3 * STG + 1024)

#define LOAD_STAGE(st, k0) do { \
    unsigned _sp = sbase + (st) * STG; \
    _Pragma("unroll") \
    for (int _i = 0; _i < 4; _i++) { \
        int _ci = tid + _i * 256; \
        int _r = _ci >> 3, _c = _ci & 7; \
        unsigned _off = (unsigned)(_r * 128) + (((unsigned)_c ^ ((unsigned)_r & 7u)) << 4); \
        size_t _ga = (size_t)(m0 + _r) * D_ + (k0) + _c * 8; \
        size_t _gb = (size_t)(n0 + _r) * D_ + (k0) + _c * 8; \
        cp16(_sp + _off,         Ah + _ga); \
        cp16(_sp + 16384 + _off, Al + _ga); \
        cp16(_sp + 32768 + _off, Bh + _gb); \
        cp16(_sp + 49152 + _off, Bl + _gb); \
    } \
} while (0)

template <int MODE>
__global__ __launch_bounds__(256, 1) void gemm_kernel(
    const float* __restrict__ vres, const float* __restrict__ bout,
    float* __restrict__ Cout)
{
    extern __shared__ char dynsm[];
    unsigned braw = smem_u32(dynsm);
    unsigned sbase = (braw + 1023) & ~1023u;

    int tid = threadIdx.x;
    int lane = tid & 31, wid = tid >> 5;
    int warp_m = wid & 3, warp_n = wid >> 2;
    int m0 = blockIdx.y * 128, n0 = blockIdx.x * 128;
    int wm = warp_m * 32, wn = warp_n * 64;

    const unsigned short* Ah = (MODE == 0) ? g_A1h : g_A2h;
    const unsigned short* Al = (MODE == 0) ? g_A1l : g_A2l;
    const unsigned short* Bh = (MODE == 0) ? g_Bqh : g_Boh;
    const unsigned short* Bl = (MODE == 0) ? g_Bql : g_Bol;

    int t4 = lane >> 3, lr = lane & 7;
    int a_row  = ((t4 & 1) << 3) + lr;
    int a_csel = t4 >> 1;
    int b_row  = ((t4 >> 1) << 3) + lr;
    int b_csel = t4 & 1;

    float acc[2][8][4];
    #pragma unroll
    for (int i = 0; i < 2; i++)
        #pragma unroll
        for (int j = 0; j < 8; j++)
            #pragma unroll
            for (int q = 0; q < 4; q++) acc[i][j][q] = 0.f;

    LOAD_STAGE(0, 0); CP_COMMIT();
    LOAD_STAGE(1, BK_); CP_COMMIT();

    #pragma unroll 1
    for (int c = 0; c < NCH; c++) {
        if (c + 2 < NCH) CP_WAIT1(); else CP_WAIT0();
        __syncthreads();
        if (c + 2 < NCH) { LOAD_STAGE((c + 2) % 3, (c + 2) * BK_); CP_COMMIT(); }

        unsigned sp = sbase + (c % 3) * STG;
        unsigned sAh = sp, sAl = sp + 16384, sBh = sp + 32768, sBl = sp + 49152;

        #pragma unroll
        for (int ks = 0; ks < 4; ks++) {
            unsigned bh[8][2], bl[8][2];
            #pragma unroll
            for (int np = 0; np < 4; np++) {
                unsigned row = (unsigned)(wn + np * 16 + b_row);
                unsigned ch = (unsigned)(ks * 2 + b_csel);
                unsigned off = row * 128 + ((ch ^ (row & 7)) << 4);
                LDM4(bh[2*np][0], bh[2*np][1], bh[2*np+1][0], bh[2*np+1][1], sBh + off);
                LDM4(bl[2*np][0], bl[2*np][1], bl[2*np+1][0], bl[2*np+1][1], sBl + off);
            }
            #pragma unroll
            for (int mt = 0; mt < 2; mt++) {
                unsigned ah0, ah1, ah2, ah3, al0, al1, al2, al3;
                unsigned row = (unsigned)(wm + mt * 16 + a_row);
                unsigned ch = (unsigned)(ks * 2 + a_csel);
                unsigned off = row * 128 + ((ch ^ (row & 7)) << 4);
                LDM4(ah0, ah1, ah2, ah3, sAh + off);
                LDM4(al0, al1, al2, al3, sAl + off);
                #pragma unroll
                for (int nt = 0; nt < 8; nt++) {
                    MMA_BF16(acc[mt][nt][0], acc[mt][nt][1], acc[mt][nt][2], acc[mt][nt][3],
                             ah0, ah1, ah2, ah3, bh[nt][0], bh[nt][1]);
                    MMA_BF16(acc[mt][nt][0], acc[mt][nt][1], acc[mt][nt][2], acc[mt][nt][3],
                             ah0, ah1, ah2, ah3, bl[nt][0], bl[nt][1]);
                    MMA_BF16(acc[mt][nt][0], acc[mt][nt][1], acc[mt][nt][2], acc[mt][nt][3],
                             al0, al1, al2, al3, bh[nt][0], bh[nt][1]);
                }
            }
        }
        __syncthreads();
    }

    // ---- epilogue ----
    #pragma unroll
    for (int mt = 0; mt < 2; mt++) {
        #pragma unroll
        for (int nt = 0; nt < 8; nt++) {
            int mrow0 = m0 + wm + mt * 16 + (lane >> 2);
            int n     = n0 + wn + nt * 8 + 2 * (lane & 3);
            #pragma unroll
            for (int half = 0; half < 2; half++) {
                int m = mrow0 + half * 8;
                float va = acc[mt][nt][2 * half];
                float vb = acc[mt][nt][2 * half + 1];
                int b = m >> 11, sg = m & 2047;
                if (MODE == 0) {
                    int seg = n >> 11;
                    int nn = n & 2047;
                    int hd = nn >> 7, d = nn & 127;
                    if (seg == 2) {
                        float mx = g_mix[(size_t)m * H_ + hd];
                        float2 vr = *(const float2*)(vres + (((size_t)(b * H_ + hd)) * S_ + sg) * DH_ + d);
                        float om = 1.0f - mx;
                        va = va * om + vr.x * mx;
                        vb = vb * om + vr.y * mx;
                    }
                    unsigned hp, lp;
                    SPLIT2X2(va, vb, hp, lp);
                    if (seg == 0) {
                        size_t idx = (((size_t)(b * H_ + hd)) * S_ + sg) * DH_ + d;
                        *(unsigned*)(g_qh + idx) = hp;
                        *(unsigned*)(g_ql + idx) = lp;
                    } else if (seg == 1) {
                        size_t idx = (((size_t)(b * H_ + hd)) * SP_ + P_ + sg) * DH_ + d;
                        *(unsigned*)(g_kh + idx) = hp;
                        *(unsigned*)(g_kl + idx) = lp;
                    } else {
                        size_t idx = (((size_t)(b * H_ + hd)) * SP_ + P_ + sg) * DH_ + d;
                        *(unsigned*)(g_vh + idx) = hp;
                        *(unsigned*)(g_vl + idx) = lp;
                    }
                } else {
                    *(float2*)(Cout + (size_t)m * D_ + n) =
                        make_float2(va + bout[n], vb + bout[n + 1]);
                }
            }
        }
    }
}

// ---------------- flash attention v3: Q128 tile, register-resident P ---------
// smem: Qh 32K | Ql 32K | KV double buffer 2 x 64K (Kh|Kl|Vh|Vl 16K each)
#define AQH 0
#define AQL 32768
#define AKV0 65536
#define ATTN_SMEM (196608 + 1024)

#define LOAD_KV(bufi, j0v) do { \
    unsigned _kb = sbase + AKV0 + (bufi) * 65536; \
    size_t _gk = (size_t)bh * SP_; \
    _Pragma("unroll") \
    for (int _i = 0; _i < 4; _i++) { \
        int _ci = tid + _i * 256; \
        int _r = _ci >> 4, _c = _ci & 15; \
        int _jg = (j0v) + _r; if (_jg > SP_ - 1) _jg = SP_ - 1; \
        unsigned _d = _kb + (unsigned)(_r * 256) + (((unsigned)_c ^ ((unsigned)_r & 7u)) << 4); \
        size_t _go = (_gk + _jg) * DH_ + _c * 8; \
        cp16(_d,         g_kh + _go); \
        cp16(_d + 16384, g_kl + _go); \
        cp16(_d + 32768, g_vh + _go); \
        cp16(_d + 49152, g_vl + _go); \
    } \
} while (0)

__global__ __launch_bounds__(256, 1) void attn_kernel()
{
    extern __shared__ char dynsm2[];
    unsigned braw = smem_u32(dynsm2);
    unsigned sbase = (braw + 1023) & ~1023u;

    int tid = threadIdx.x;
    int lane = tid & 31, wid = tid >> 5;
    int qt = blockIdx.x, h = blockIdx.y, b = blockIdx.z;
    int bh = b * H_ + h;
    int qbase = qt * 128;

    // ---- Q load (128 rows x 128 dh, hi+lo) ----
    {
        size_t gq = (size_t)bh * S_ + qbase;
        #pragma unroll
        for (int i = 0; i < 8; i++) {
            int ci = tid + i * 256;
            int r = ci >> 4, c = ci & 15;
            unsigned dst = sbase + AQH + (unsigned)(r * 256) + (((unsigned)c ^ ((unsigned)r & 7u)) << 4);
            cp16(dst,         g_qh + (gq + r) * DH_ + c * 8);
            cp16(dst + 32768, g_ql + (gq + r) * DH_ + c * 8);
        }
    }
    LOAD_KV(0, 0);
    CP_COMMIT();

    float oacc[16][4];
    #pragma unroll
    for (int i = 0; i < 16; i++)
        #pragma unroll
        for (int q = 0; q < 4; q++) oacc[i][q] = 0.f;
    float mrow0 = -INFINITY, mrow1 = -INFINITY, lrow0 = 0.f, lrow1 = 0.f;

    const float scale = 0.08838834764831845f;
    int ntiles = (P_ + qbase + 128 + 63) >> 6;

    int t4 = lane >> 3, lr = lane & 7;
    int a_row  = ((t4 & 1) << 3) + lr;
    int a_csel = t4 >> 1;
    int b_row  = ((t4 >> 1) << 3) + lr;
    int b_csel = t4 & 1;
    int r_b = lane >> 2, c_b = (lane & 3) * 2;
    int wmQ = wid * 16;
    int ig0 = qbase + wmQ + r_b;        // row of frag elems 0,1
    int ig1 = ig0 + 8;                  // row of frag elems 2,3

    #pragma unroll 1
    for (int t = 0; t < ntiles; t++) {
        int j0 = t << 6;
        if (t + 1 < ntiles) { LOAD_KV((t + 1) & 1, (t + 1) * 64); CP_COMMIT(); CP_WAIT1(); }
        else CP_WAIT0();
        __syncthreads();

        unsigned kvb = sbase + AKV0 + (t & 1) * 65536;

        // ---- S = Q K^T (3-term); each warp: its 16 rows x all 64 kv cols ----
        float sacc[8][4];
        #pragma unroll
        for (int i = 0; i < 8; i++)
            #pragma unroll
            for (int q = 0; q < 4; q++) sacc[i][q] = 0.f;

        #pragma unroll
        for (int ks = 0; ks < 8; ks++) {
            unsigned kh[8][2], kl[8][2];
            #pragma unroll
            for (int g = 0; g < 4; g++) {
                unsigned row = (unsigned)(g * 16 + b_row);
                unsigned ch = (unsigned)(ks * 2 + b_csel);
                unsigned addr = kvb + row * 256 + ((ch ^ (row & 7)) << 4);
                LDM4(kh[2*g][0], kh[2*g][1], kh[2*g+1][0], kh[2*g+1][1], addr);
                LDM4(kl[2*g][0], kl[2*g][1], kl[2*g+1][0], kl[2*g+1][1], addr + 16384);
            }
            unsigned qh0, qh1, qh2, qh3, ql0, ql1, ql2, ql3;
            {
                unsigned row = (unsigned)(wmQ + a_row);
                unsigned ch = (unsigned)(ks * 2 + a_csel);
                unsigned addr = sbase + AQH + row * 256 + ((ch ^ (row & 7)) << 4);
                LDM4(qh0, qh1, qh2, qh3, addr);
                LDM4(ql0, ql1, ql2, ql3, addr + 32768);
            }
            #pragma unroll
            for (int n8 = 0; n8 < 8; n8++) {
                MMA_BF16(sacc[n8][0], sacc[n8][1], sacc[n8][2], sacc[n8][3],
                         qh0, qh1, qh2, qh3, kh[n8][0], kh[n8][1]);
                MMA_BF16(sacc[n8][0], sacc[n8][1], sacc[n8][2], sacc[n8][3],
                         qh0, qh1, qh2, qh3, kl[n8][0], kl[n8][1]);
                MMA_BF16(sacc[n8][0], sacc[n8][1], sacc[n8][2], sacc[n8][3],
                         ql0, ql1, ql2, ql3, kh[n8][0], kh[n8][1]);
            }
        }

        // ---- scale + mask (registers) ----
        #pragma unroll
        for (int n8 = 0; n8 < 8; n8++) {
            int jg0 = j0 + n8 * 8 + c_b;
            #pragma unroll
            for (int e = 0; e < 2; e++) {
                int jg = jg0 + e;
                float sv0 = sacc[n8][e] * scale;
                float sv1 = sacc[n8][2 + e] * scale;
                if (jg >= P_ && (jg - P_) > ig0) sv0 = -1e30f;
                if (jg >= P_ && (jg - P_) > ig1) sv1 = -1e30f;
                sacc[n8][e] = sv0;
                sacc[n8][2 + e] = sv1;
            }
        }

        // ---- register softmax (rows owned by 4-lane quads) ----
        float mx0 = -1e30f, mx1 = -1e30f;
        #pragma unroll
        for (int n8 = 0; n8 < 8; n8++) {
            mx0 = fmaxf(mx0, fmaxf(sacc[n8][0], sacc[n8][1]));
            mx1 = fmaxf(mx1, fmaxf(sacc[n8][2], sacc[n8][3]));
        }
        mx0 = fmaxf(mx0, __shfl_xor_sync(0xffffffffu, mx0, 1));
        mx0 = fmaxf(mx0, __shfl_xor_sync(0xffffffffu, mx0, 2));
        mx1 = fmaxf(mx1, __shfl_xor_sync(0xffffffffu, mx1, 1));
        mx1 = fmaxf(mx1, __shfl_xor_sync(0xffffffffu, mx1, 2));
        float mn0 = fmaxf(mrow0, mx0), mn1 = fmaxf(mrow1, mx1);
        float cor0 = __expf(mrow0 - mn0), cor1 = __expf(mrow1 - mn1);
        mrow0 = mn0; mrow1 = mn1;

        float sum0 = 0.f, sum1 = 0.f;
        #pragma unroll
        for (int n8 = 0; n8 < 8; n8++) {
            float p0 = __expf(sacc[n8][0] - mn0);
            float p1 = __expf(sacc[n8][1] - mn0);
            float p2 = __expf(sacc[n8][2] - mn1);
            float p3 = __expf(sacc[n8][3] - mn1);
            sum0 += p0 + p1; sum1 += p2 + p3;
            sacc[n8][0] = p0; sacc[n8][1] = p1; sacc[n8][2] = p2; sacc[n8][3] = p3;
        }
        sum0 += __shfl_xor_sync(0xffffffffu, sum0, 1);
        sum0 += __shfl_xor_sync(0xffffffffu, sum0, 2);
        sum1 += __shfl_xor_sync(0xffffffffu, sum1, 1);
        sum1 += __shfl_xor_sync(0xffffffffu, sum1, 2);
        lrow0 = lrow0 * cor0 + sum0;
        lrow1 = lrow1 * cor1 + sum1;

        // ---- pack P into A-operand fragments (C-frag == A-frag layout) ----
        unsigned pph[4][4], ppl[4][4];
        #pragma unroll
        for (int ks = 0; ks < 4; ks++) {
            SPLIT2X2(sacc[2*ks][0],   sacc[2*ks][1],   pph[ks][0], ppl[ks][0]);
            SPLIT2X2(sacc[2*ks][2],   sacc[2*ks][3],   pph[ks][1], ppl[ks][1]);
            SPLIT2X2(sacc[2*ks+1][0], sacc[2*ks+1][1], pph[ks][2], ppl[ks][2]);
            SPLIT2X2(sacc[2*ks+1][2], sacc[2*ks+1][3], pph[ks][3], ppl[ks][3]);
        }

        // ---- O *= corr ----
        #pragma unroll
        for (int n8 = 0; n8 < 16; n8++) {
            oacc[n8][0] *= cor0; oacc[n8][1] *= cor0;
            oacc[n8][2] *= cor1; oacc[n8][3] *= cor1;
        }

        // ---- O += P V (3-term); V via ldmatrix.trans ----
        unsigned sVh = kvb + 32768;
        #pragma unroll
        for (int ks = 0; ks < 4; ks++) {
            #pragma unroll
            for (int half = 0; half < 2; half++) {
                unsigned vh[8][2], vl[8][2];
                unsigned krow = (unsigned)(ks * 16 + (lane & 15));
                unsigned chx = (unsigned)(lane >> 4);
                #pragma unroll
                for (int pi = 0; pi < 4; pi++) {
                    unsigned ch = (unsigned)((half * 4 + pi) * 2) + chx;
                    unsigned addr = sVh + krow * 256 + ((ch ^ (krow & 7)) << 4);
                    LDM4T(vh[2*pi][0], vh[2*pi][1], vh[2*pi+1][0], vh[2*pi+1][1], addr);
                    LDM4T(vl[2*pi][0], vl[2*pi][1], vl[2*pi+1][0], vl[2*pi+1][1], addr + 16384);
                }
                #pragma unroll
                for (int j = 0; j < 8; j++) {
                    int n8 = half * 8 + j;
                    MMA_BF16(oacc[n8][0], oacc[n8][1], oacc[n8][2], oacc[n8][3],
                             pph[ks][0], pph[ks][1], pph[ks][2], pph[ks][3],
                             vh[j][0], vh[j][1]);
                    MMA_BF16(oacc[n8][0], oacc[n8][1], oacc[n8][2], oacc[n8][3],
                             pph[ks][0], pph[ks][1], pph[ks][2], pph[ks][3],
                             vl[j][0], vl[j][1]);
                    MMA_BF16(oacc[n8][0], oacc[n8][1], oacc[n8][2], oacc[n8][3],
                             ppl[ks][0], ppl[ks][1], ppl[ks][2], ppl[ks][3],
                             vh[j][0], vh[j][1]);
                }
            }
        }
        __syncthreads();   // all warps done with this KV buffer before next prefetch overwrites it
    }

    // ---- final: scale by 1/l, split, store ----
    float li0 = 1.0f / lrow0;
    float li1 = 1.0f / lrow1;
    size_t ro0 = ((size_t)(b * S_ + qbase + wmQ + r_b)) * D_ + h * DH_;
    size_t ro1 = ro0 + (size_t)8 * D_;
    #pragma unroll
    for (int n8 = 0; n8 < 16; n8++) {
        int c = n8 * 8 + c_b;
        unsigned hp, lp;
        SPLIT2X2(oacc[n8][0] * li0, oacc[n8][1] * li0, hp, lp);
        *(unsigned*)(g_A2h + ro0 + c) = hp;
        *(unsigned*)(g_A2l + ro0 + c) = lp;
        SPLIT2X2(oacc[n8][2] * li1, oacc[n8][3] * li1, hp, lp);
        *(unsigned*)(g_A2h + ro1 + c) = hp;
        *(unsigned*)(g_A2l + ro1 + c) = lp;
    }
}

// ---------------- launch ------------------------------------------------------
extern "C" void kernel_launch(void* const* d_in, const int* in_sizes, int n_in,
                              void* d_out, int out_size)
{
    const float* x    = (const float*)d_in[0];
    const float* vres = (const float*)d_in[1];
    const float* lng  = (const float*)d_in[2];
    const float* lnb  = (const float*)d_in[3];
    const float* wqkv = (const float*)d_in[4];
    const float* wout = (const float*)d_in[5];
    const float* bout = (const float*)d_in[6];
    const float* wmix = (const float*)d_in[7];
    const float* bmix = (const float*)d_in[8];
    const float* pmem = (const float*)d_in[9];
    float* out = (float*)d_out;

    cudaFuncSetAttribute(attn_kernel, cudaFuncAttributeMaxDynamicSharedMemorySize, ATTN_SMEM);
    cudaFuncSetAttribute(gemm_kernel<0>, cudaFuncAttributeMaxDynamicSharedMemorySize, GEMM_SMEM);
    cudaFuncSetAttribute(gemm_kernel<1>, cudaFuncAttributeMaxDynamicSharedMemorySize, GEMM_SMEM);

    ln_mix_kernel<<<BS_, 256>>>(x, lng, lnb, wmix, bmix);
    transconv_kernel<0><<<dim3(3 * D_ / 32, D_ / 32), 256>>>(wqkv);
    transconv_kernel<1><<<dim3(D_ / 32, D_ / 32), 256>>>(wout);
    pmem_kernel<<<256, 256>>>(pmem);
    gemm_kernel<0><<<dim3(3 * D_ / 128, BS_ / 128), 256, GEMM_SMEM>>>(vres, nullptr, nullptr);
    attn_kernel<<<dim3(S_ / 128, H_, B_), 256, ATTN_SMEM>>>();
    gemm_kernel<1><<<dim3(D_ / 128, BS_ / 128), 256, GEMM_SMEM>>>(nullptr, bout, out);
}